// round 6
// baseline (speedup 1.0000x reference)
#include <cuda_runtime.h>
#include <cuda_bf16.h>
#include <cstdint>

#define L_SEQ 512
#define D_MODEL 1024
#define N_HEADS 16

// ---------------- scratch (__device__ globals) ----------------
__device__ __nv_bfloat16 g_x_hi[(size_t)8192 * 1024];
__device__ __nv_bfloat16 g_x_lo[(size_t)8192 * 1024];
__device__ __nv_bfloat16 g_wqkvT_hi[(size_t)3072 * 1024];
__device__ __nv_bfloat16 g_wqkvT_lo[(size_t)3072 * 1024];
__device__ __nv_bfloat16 g_woutT_hi[(size_t)1024 * 1024];
__device__ __nv_bfloat16 g_woutT_lo[(size_t)1024 * 1024];
__device__ __nv_bfloat16 g_qkv_hi[(size_t)8192 * 3072];
__device__ __nv_bfloat16 g_qkv_lo[(size_t)8192 * 3072];
__device__ __nv_bfloat16 g_attn_hi[(size_t)8192 * 1024];
__device__ __nv_bfloat16 g_attn_lo[(size_t)8192 * 1024];

// ---------------- PTX helpers ----------------
__device__ __forceinline__ uint32_t smem_u32(const void* p) {
    uint32_t a;
    asm("{ .reg .u64 t; cvta.to.shared.u64 t, %1; cvt.u32.u64 %0, t; }" : "=r"(a) : "l"(p));
    return a;
}

#define CP_ASYNC16(dst, src) \
    asm volatile("cp.async.cg.shared.global [%0], [%1], 16;" :: "r"(dst), "l"(src))
#define CP_COMMIT() asm volatile("cp.async.commit_group;" ::: "memory")
#define CP_WAIT2()  asm volatile("cp.async.wait_group 2;" ::: "memory")
#define CP_WAIT0()  asm volatile("cp.async.wait_group 0;" ::: "memory")

#define LDMATRIX_X4(r, addr) \
    asm volatile("ldmatrix.sync.aligned.m8n8.x4.shared.b16 {%0,%1,%2,%3}, [%4];" \
                 : "=r"((r)[0]), "=r"((r)[1]), "=r"((r)[2]), "=r"((r)[3]) : "r"(addr))
#define LDMATRIX_X4_TRANS(r, addr) \
    asm volatile("ldmatrix.sync.aligned.m8n8.x4.trans.shared.b16 {%0,%1,%2,%3}, [%4];" \
                 : "=r"((r)[0]), "=r"((r)[1]), "=r"((r)[2]), "=r"((r)[3]) : "r"(addr))

#define MMA16816(c, a, b) \
    asm volatile("mma.sync.aligned.m16n8k16.row.col.f32.bf16.bf16.f32 " \
                 "{%0,%1,%2,%3},{%4,%5,%6,%7},{%8,%9},{%0,%1,%2,%3};" \
                 : "+f"((c)[0]), "+f"((c)[1]), "+f"((c)[2]), "+f"((c)[3]) \
                 : "r"((a)[0]), "r"((a)[1]), "r"((a)[2]), "r"((a)[3]), \
                   "r"((b)[0]), "r"((b)[1]))

__device__ __forceinline__ uint32_t pack_bf16x2(float a, float b) {
    __nv_bfloat162 t = __floats2bfloat162_rn(a, b);
    return *reinterpret_cast<uint32_t*>(&t);
}

// ---------------- prepass ----------------
__global__ __launch_bounds__(256) void split_kernel(
    const float* __restrict__ in, __nv_bfloat16* __restrict__ hi,
    __nv_bfloat16* __restrict__ lo, int n)
{
    int i = blockIdx.x * 256 + threadIdx.x;
    if (i < n) {
        float v = in[i];
        __nv_bfloat16 h = __float2bfloat16(v);
        hi[i] = h;
        lo[i] = __float2bfloat16(v - __bfloat162float(h));
    }
}

__global__ __launch_bounds__(256) void tsplit_kernel(
    const float* __restrict__ in, __nv_bfloat16* __restrict__ ohi,
    __nv_bfloat16* __restrict__ olo, int R, int C)
{
    __shared__ float t[32][33];
    int c0 = blockIdx.x * 32, r0 = blockIdx.y * 32;
    int x = threadIdx.x, y = threadIdx.y;
#pragma unroll
    for (int i = 0; i < 32; i += 8)
        t[y + i][x] = in[(size_t)(r0 + y + i) * C + c0 + x];
    __syncthreads();
#pragma unroll
    for (int i = 0; i < 32; i += 8) {
        float v = t[x][y + i];
        __nv_bfloat16 h = __float2bfloat16(v);
        size_t o = (size_t)(c0 + y + i) * R + r0 + x;
        ohi[o] = h;
        olo[o] = __float2bfloat16(v - __bfloat162float(h));
    }
}

// ---------------- HMMA bf16x2 GEMM: 4-stage cp.async pipeline, BK=16 ----------------
#define BM 128
#define BN 128
#define BK 16
#define ROW_B 48                       // 32B data + 16 pad: conflict-free ldmatrix
#define COMP_BYTES (128 * ROW_B)       // 6144
#define STAGE_BYTES (4 * COMP_BYTES)   // 24576
#define GEMM_SMEM (4 * STAGE_BYTES)    // 98304

__global__ __launch_bounds__(256, 2) void gemm_bf16x2_kernel(
    const __nv_bfloat16* __restrict__ Ahi, const __nv_bfloat16* __restrict__ Alo,
    const __nv_bfloat16* __restrict__ Bhi, const __nv_bfloat16* __restrict__ Blo,
    const float* __restrict__ bias, float* __restrict__ C,
    __nv_bfloat16* __restrict__ Chi, __nv_bfloat16* __restrict__ Clo,
    int M, int N, int K)
{
    extern __shared__ char smem[];
    const uint32_t sbase = smem_u32(smem);
    const int tid = threadIdx.x, wid = tid >> 5, lane = tid & 31;
    const int bm = blockIdx.y * BM, bn = blockIdx.x * BN;
    const int warp_m = (wid >> 2) * 64, warp_n = (wid & 3) * 32;
    const int NT = K / BK;

    float acc[4][4][4];
#pragma unroll
    for (int i = 0; i < 4; i++)
#pragma unroll
        for (int j = 0; j < 4; j++)
#pragma unroll
            for (int r = 0; r < 4; r++) acc[i][j][r] = 0.f;

    const __nv_bfloat16* srcs[4] = {Ahi, Alo, Bhi, Blo};
    const int ld_row = tid >> 1, ld_ch = tid & 1;   // 1 chunk per comp per thread

    auto issue = [&](int s, int kt) {
        const uint32_t dst0 = sbase + s * STAGE_BYTES;
        const int k0 = kt * BK;
#pragma unroll
        for (int comp = 0; comp < 4; comp++) {
            const int rbase = (comp < 2) ? bm : bn;
            const __nv_bfloat16* g =
                srcs[comp] + (size_t)(rbase + ld_row) * K + k0 + ld_ch * 8;
            CP_ASYNC16(dst0 + comp * COMP_BYTES + ld_row * ROW_B + ld_ch * 16, g);
        }
    };

    const int lr = lane & 15, lk = lane >> 4;
    const int brow = (lane & 7) + ((lane >> 4) << 3);
    const int bsel = ((lane >> 3) & 1) << 4;

    auto compute = [&](int s) {
        const uint32_t st = sbase + s * STAGE_BYTES;
        uint32_t bh[4][2], bl[4][2];
#pragma unroll
        for (int ntp = 0; ntp < 2; ntp++) {
            uint32_t baddr = st + 2 * COMP_BYTES + (warp_n + ntp * 16 + brow) * ROW_B + bsel;
            uint32_t r4[4];
            LDMATRIX_X4(r4, baddr);
            bh[2 * ntp][0] = r4[0]; bh[2 * ntp][1] = r4[1];
            bh[2 * ntp + 1][0] = r4[2]; bh[2 * ntp + 1][1] = r4[3];
            LDMATRIX_X4(r4, baddr + COMP_BYTES);
            bl[2 * ntp][0] = r4[0]; bl[2 * ntp][1] = r4[1];
            bl[2 * ntp + 1][0] = r4[2]; bl[2 * ntp + 1][1] = r4[3];
        }
#pragma unroll
        for (int mt = 0; mt < 4; mt++) {
            uint32_t aaddr = st + (warp_m + mt * 16 + lr) * ROW_B + lk * 16;
            uint32_t ah[4], al[4];
            LDMATRIX_X4(ah, aaddr);
            LDMATRIX_X4(al, aaddr + COMP_BYTES);
#pragma unroll
            for (int nt = 0; nt < 4; nt++) {
                MMA16816(acc[mt][nt], ah, bh[nt]);
                MMA16816(acc[mt][nt], ah, bl[nt]);
                MMA16816(acc[mt][nt], al, bh[nt]);
            }
        }
    };

    // Prologue: 3 tiles in flight
    issue(0, 0); CP_COMMIT();
    issue(1, 1); CP_COMMIT();
    issue(2, 2); CP_COMMIT();

    for (int kt = 0; kt < NT; kt++) {
        CP_WAIT2();            // tile kt resident
        __syncthreads();       // all warps done reading stage (kt+3)&3 from iter kt-1
        if (kt + 3 < NT) issue((kt + 3) & 3, kt + 3);
        CP_COMMIT();
        compute(kt & 3);
    }

#pragma unroll
    for (int mt = 0; mt < 4; mt++) {
        int row0 = bm + warp_m + mt * 16 + (lane >> 2);
#pragma unroll
        for (int nt = 0; nt < 4; nt++) {
            int col = bn + warp_n + nt * 8 + 2 * (lane & 3);
            if (Chi) {
#pragma unroll
                for (int half = 0; half < 2; half++) {
                    float v0 = acc[mt][nt][2 * half];
                    float v1 = acc[mt][nt][2 * half + 1];
                    __nv_bfloat16 h0 = __float2bfloat16(v0);
                    __nv_bfloat16 h1 = __float2bfloat16(v1);
                    __nv_bfloat162 hp; hp.x = h0; hp.y = h1;
                    __nv_bfloat162 lp;
                    lp.x = __float2bfloat16(v0 - __bfloat162float(h0));
                    lp.y = __float2bfloat16(v1 - __bfloat162float(h1));
                    size_t o = (size_t)(row0 + half * 8) * N + col;
                    *reinterpret_cast<__nv_bfloat162*>(&Chi[o]) = hp;
                    *reinterpret_cast<__nv_bfloat162*>(&Clo[o]) = lp;
                }
            } else {
                float b0 = 0.f, b1 = 0.f;
                if (bias) { b0 = bias[col]; b1 = bias[col + 1]; }
                float2 v0 = make_float2(acc[mt][nt][0] + b0, acc[mt][nt][1] + b1);
                float2 v1 = make_float2(acc[mt][nt][2] + b0, acc[mt][nt][3] + b1);
                *reinterpret_cast<float2*>(&C[(size_t)row0 * N + col]) = v0;
                *reinterpret_cast<float2*>(&C[(size_t)(row0 + 8) * N + col]) = v1;
            }
        }
    }
}

// ---------------- FlashAttention-style fused attention, MQ=64, 512 threads ----------------
#define AT_V    36864     // Khi|Klo at 0 (18432 each); Vhi|Vlo here
#define AT_Q    73728     // Qhi[64][144] (9216) | Qlo (9216)
#define AT_REL  92160
#define AT_RS   93184     // [4][64] floats
#define ATTN_SMEM 94208
#define AT_P4   0         // reuse K/V after last tile: [4][64][68] fp32 = 69632

__global__ __launch_bounds__(512) void attn_flash_kernel(const float* __restrict__ rel_emb)
{
    extern __shared__ char smc[];
    const uint32_t sb = smem_u32(smc);
    float* Rel = (float*)(smc + AT_REL);
    float* RS  = (float*)(smc + AT_RS);
    float* P4  = (float*)(smc + AT_P4);

    const int tid = threadIdx.x, wid = tid >> 5, lane = tid & 31;
    const int pair = blockIdx.y, bt = pair >> 4, h = pair & 15;
    const int q0 = blockIdx.x * 64;
    const int wm = wid >> 2, wn = wid & 3;       // 4m x 4n warps
    const int gr = lane >> 2, gc = lane & 3;
    const int lr = lane & 15, lk = lane >> 4;
    const int xrow = (lane & 7) + ((lane >> 4) << 3);
    const int xsel = ((lane >> 3) & 1) << 4;

    const __nv_bfloat16* ghi = g_qkv_hi + (size_t)bt * 512 * 3072 + h * 64;
    const __nv_bfloat16* glo = g_qkv_lo + (size_t)bt * 512 * 3072 + h * 64;

    auto issue_kv = [&](int t) {
#pragma unroll
        for (int i = 0; i < 9; i++) {
            int c = i * 512 + tid;
            int sec = c / 1152, rem = c - sec * 1152;
            int row = rem / 9, ch = rem - row * 9;
            const __nv_bfloat16* base = (sec & 1) ? glo : ghi;
            int comp_off = (sec < 2) ? 1024 : 2048;   // K : V
            const __nv_bfloat16* src =
                base + (size_t)(t * 128 + row) * 3072 + comp_off + ch * 8;
            CP_ASYNC16(sb + sec * 18432 + row * 144 + ch * 16, src);
        }
    };

    issue_kv(0); CP_COMMIT();

    {
        __nv_bfloat16* Qh = (__nv_bfloat16*)(smc + AT_Q);
        __nv_bfloat16* Ql = (__nv_bfloat16*)(smc + AT_Q + 9216);
        for (int idx = tid; idx < 4096; idx += 512) {
            int i = idx >> 6, d = idx & 63;
            size_t g = (size_t)(q0 + i) * 3072 + d;
            Qh[i * 72 + d] = __float2bfloat16(0.125f * __bfloat162float(ghi[g]));
            Ql[i * 72 + d] = __float2bfloat16(0.125f * __bfloat162float(glo[g]));
        }
        if (tid < 255) Rel[tid] = rel_emb[tid * N_HEADS + h];
    }
    CP_WAIT0();
    __syncthreads();

    uint32_t qh[4][4], ql[4][4];
    {
        uint32_t qa = sb + AT_Q + (wm * 16 + lr) * 144 + lk * 16;
#pragma unroll
        for (int ks = 0; ks < 4; ks++) {
            LDMATRIX_X4(qh[ks], qa + ks * 32);
            LDMATRIX_X4(ql[ks], qa + 9216 + ks * 32);
        }
    }

    float o[8][4];
#pragma unroll
    for (int n = 0; n < 8; n++)
#pragma unroll
        for (int r = 0; r < 4; r++) o[n][r] = 0.f;
    float sum0 = 0.f, sum1 = 0.f;

    for (int t = 0; t < 4; t++) {
        if (t > 0) {
            issue_kv(t); CP_COMMIT();
            CP_WAIT0();
            __syncthreads();
        }

        float acc[4][4];
#pragma unroll
        for (int nt = 0; nt < 4; nt++)
#pragma unroll
            for (int r = 0; r < 4; r++) acc[nt][r] = 0.f;

#pragma unroll
        for (int ks = 0; ks < 4; ks++) {
            uint32_t bh[4][2], bl[4][2];
#pragma unroll
            for (int ntp = 0; ntp < 2; ntp++) {
                uint32_t baddr = sb + (wn * 32 + ntp * 16 + xrow) * 144 + xsel + ks * 32;
                uint32_t r4[4];
                LDMATRIX_X4(r4, baddr);
                bh[2 * ntp][0] = r4[0]; bh[2 * ntp][1] = r4[1];
                bh[2 * ntp + 1][0] = r4[2]; bh[2 * ntp + 1][1] = r4[3];
                LDMATRIX_X4(r4, baddr + 18432);
                bl[2 * ntp][0] = r4[0]; bl[2 * ntp][1] = r4[1];
                bl[2 * ntp + 1][0] = r4[2]; bl[2 * ntp + 1][1] = r4[3];
            }
#pragma unroll
            for (int nt = 0; nt < 4; nt++) {
                MMA16816(acc[nt], qh[ks], bh[nt]);
                MMA16816(acc[nt], qh[ks], bl[nt]);
                MMA16816(acc[nt], ql[ks], bh[nt]);
            }
        }

        uint32_t pfh[2][4], pfl[2][4];
#pragma unroll
        for (int nt = 0; nt < 4; nt++) {
            int gs = t * 128 + wn * 32 + nt * 8 + 2 * gc;
            int gq0 = q0 + wm * 16 + gr, gq1 = gq0 + 8;
            float e00 = __expf(acc[nt][0] + Rel[min(max(gq0 - gs,     -127), 127) + 127]);
            float e01 = __expf(acc[nt][1] + Rel[min(max(gq0 - gs - 1, -127), 127) + 127]);
            float e10 = __expf(acc[nt][2] + Rel[min(max(gq1 - gs,     -127), 127) + 127]);
            float e11 = __expf(acc[nt][3] + Rel[min(max(gq1 - gs - 1, -127), 127) + 127]);
            sum0 += e00 + e01;
            sum1 += e10 + e11;
            __nv_bfloat162 h0 = __floats2bfloat162_rn(e00, e01);
            __nv_bfloat162 h1 = __floats2bfloat162_rn(e10, e11);
            uint32_t ph0 = *reinterpret_cast<uint32_t*>(&h0);
            uint32_t ph1 = *reinterpret_cast<uint32_t*>(&h1);
            uint32_t pl0 = pack_bf16x2(e00 - __bfloat162float(h0.x), e01 - __bfloat162float(h0.y));
            uint32_t pl1 = pack_bf16x2(e10 - __bfloat162float(h1.x), e11 - __bfloat162float(h1.y));
            int kc = nt >> 1, hi2 = (nt & 1) << 1;
            pfh[kc][hi2] = ph0; pfh[kc][hi2 + 1] = ph1;
            pfl[kc][hi2] = pl0; pfl[kc][hi2 + 1] = pl1;
        }

#pragma unroll
        for (int kc = 0; kc < 2; kc++) {
#pragma unroll
            for (int dp = 0; dp < 4; dp++) {
                uint32_t va = sb + AT_V +
                    (wn * 32 + kc * 16 + (lane & 7) + (((lane >> 3) & 1) << 3)) * 144 +
                    (dp * 16 + ((lane >> 4) << 3)) * 2;
                uint32_t r4[4];
                LDMATRIX_X4_TRANS(r4, va);
                uint32_t vh0[2] = {r4[0], r4[1]}, vh1[2] = {r4[2], r4[3]};
                LDMATRIX_X4_TRANS(r4, va + 18432);
                uint32_t vl0[2] = {r4[0], r4[1]}, vl1[2] = {r4[2], r4[3]};
                MMA16816(o[2 * dp],     pfh[kc], vh0);
                MMA16816(o[2 * dp],     pfh[kc], vl0);
                MMA16816(o[2 * dp],     pfl[kc], vh0);
                MMA16816(o[2 * dp + 1], pfh[kc], vh1);
                MMA16816(o[2 * dp + 1], pfh[kc], vl1);
                MMA16816(o[2 * dp + 1], pfl[kc], vh1);
            }
        }
        __syncthreads();
    }

    sum0 += __shfl_xor_sync(0xffffffffu, sum0, 1);
    sum0 += __shfl_xor_sync(0xffffffffu, sum0, 2);
    sum1 += __shfl_xor_sync(0xffffffffu, sum1, 1);
    sum1 += __shfl_xor_sync(0xffffffffu, sum1, 2);
    if (gc == 0) {
        RS[wn * 64 + wm * 16 + gr] = sum0;
        RS[wn * 64 + wm * 16 + gr + 8] = sum1;
    }
#pragma unroll
    for (int nt = 0; nt < 8; nt++) {
        int d = nt * 8 + 2 * gc;
        int r0 = wm * 16 + gr;
        *reinterpret_cast<float2*>(&P4[(wn * 64 + r0) * 68 + d]) =
            make_float2(o[nt][0], o[nt][1]);
        *reinterpret_cast<float2*>(&P4[(wn * 64 + r0 + 8) * 68 + d]) =
            make_float2(o[nt][2], o[nt][3]);
    }
    __syncthreads();

    {
        int i0 = tid * 8;
        int r = i0 >> 6, d0 = i0 & 63;
        float inv = 1.f / (RS[r] + RS[64 + r] + RS[128 + r] + RS[192 + r]);
        size_t row = (size_t)bt * 512 + q0 + r;
        size_t ob = row * 1024 + h * 64 + d0;
#pragma unroll
        for (int j = 0; j < 8; j += 2) {
            float v0 = (P4[r * 68 + d0 + j] + P4[(64 + r) * 68 + d0 + j] +
                        P4[(128 + r) * 68 + d0 + j] + P4[(192 + r) * 68 + d0 + j]) * inv;
            float v1 = (P4[r * 68 + d0 + j + 1] + P4[(64 + r) * 68 + d0 + j + 1] +
                        P4[(128 + r) * 68 + d0 + j + 1] + P4[(192 + r) * 68 + d0 + j + 1]) * inv;
            __nv_bfloat16 h0 = __float2bfloat16(v0);
            __nv_bfloat16 h1 = __float2bfloat16(v1);
            __nv_bfloat162 hp; hp.x = h0; hp.y = h1;
            __nv_bfloat162 lp;
            lp.x = __float2bfloat16(v0 - __bfloat162float(h0));
            lp.y = __float2bfloat16(v1 - __bfloat162float(h1));
            *reinterpret_cast<__nv_bfloat162*>(&g_attn_hi[ob + j]) = hp;
            *reinterpret_cast<__nv_bfloat162*>(&g_attn_lo[ob + j]) = lp;
        }
    }
}

// ---------------- launch ----------------
extern "C" void kernel_launch(void* const* d_in, const int* in_sizes, int n_in,
                              void* d_out, int out_size)
{
    const float* x       = (const float*)d_in[0];
    const float* w_qkv   = (const float*)d_in[1];
    const float* rel_emb = (const float*)d_in[2];
    const float* w_out   = (const float*)d_in[3];
    const float* b_out   = (const float*)d_in[4];
    float* out = (float*)d_out;

    __nv_bfloat16 *xh, *xl, *wqh, *wql, *woh, *wol, *qh, *ql, *ah, *al;
    cudaGetSymbolAddress((void**)&xh, g_x_hi);
    cudaGetSymbolAddress((void**)&xl, g_x_lo);
    cudaGetSymbolAddress((void**)&wqh, g_wqkvT_hi);
    cudaGetSymbolAddress((void**)&wql, g_wqkvT_lo);
    cudaGetSymbolAddress((void**)&woh, g_woutT_hi);
    cudaGetSymbolAddress((void**)&wol, g_woutT_lo);
    cudaGetSymbolAddress((void**)&qh, g_qkv_hi);
    cudaGetSymbolAddress((void**)&ql, g_qkv_lo);
    cudaGetSymbolAddress((void**)&ah, g_attn_hi);
    cudaGetSymbolAddress((void**)&al, g_attn_lo);

    cudaFuncSetAttribute(attn_flash_kernel, cudaFuncAttributeMaxDynamicSharedMemorySize, ATTN_SMEM);
    cudaFuncSetAttribute(gemm_bf16x2_kernel, cudaFuncAttributeMaxDynamicSharedMemorySize, GEMM_SMEM);

    const int nx = 8192 * 1024;
    split_kernel<<<(nx + 255) / 256, 256>>>(x, xh, xl, nx);
    tsplit_kernel<<<dim3(3072 / 32, 1024 / 32), dim3(32, 8)>>>(w_qkv, wqh, wql, 1024, 3072);
    tsplit_kernel<<<dim3(1024 / 32, 1024 / 32), dim3(32, 8)>>>(w_out, woh, wol, 1024, 1024);

    gemm_bf16x2_kernel<<<dim3(3072 / BN, 8192 / BM), 256, GEMM_SMEM>>>(
        xh, xl, wqh, wql, nullptr, nullptr, qh, ql, 8192, 3072, 1024);

    attn_flash_kernel<<<dim3(L_SEQ / 64, 16 * N_HEADS), 512, ATTN_SMEM>>>(rel_emb);

    gemm_bf16x2_kernel<<<dim3(1024 / BN, 8192 / BM), 256, GEMM_SMEM>>>(
        ah, al, woh, wol, b_out, out, nullptr, nullptr, 8192, 1024, 1024);
}

// round 7
// speedup vs baseline: 1.2350x; 1.2350x over previous
#include <cuda_runtime.h>
#include <cuda_bf16.h>
#include <cstdint>

#define L_SEQ 512
#define D_MODEL 1024
#define N_HEADS 16

// ---------------- scratch (__device__ globals) ----------------
__device__ __nv_bfloat16 g_x_hi[(size_t)8192 * 1024];
__device__ __nv_bfloat16 g_x_lo[(size_t)8192 * 1024];
__device__ __nv_bfloat16 g_wqkvT_hi[(size_t)3072 * 1024];
__device__ __nv_bfloat16 g_wqkvT_lo[(size_t)3072 * 1024];
__device__ __nv_bfloat16 g_woutT_hi[(size_t)1024 * 1024];
__device__ __nv_bfloat16 g_woutT_lo[(size_t)1024 * 1024];
__device__ __nv_bfloat16 g_qkv_hi[(size_t)8192 * 3072];
__device__ __nv_bfloat16 g_qkv_lo[(size_t)8192 * 3072];
__device__ __nv_bfloat16 g_attn_hi[(size_t)8192 * 1024];
__device__ __nv_bfloat16 g_attn_lo[(size_t)8192 * 1024];

// ---------------- PTX helpers ----------------
__device__ __forceinline__ uint32_t smem_u32(const void* p) {
    uint32_t a;
    asm("{ .reg .u64 t; cvta.to.shared.u64 t, %1; cvt.u32.u64 %0, t; }" : "=r"(a) : "l"(p));
    return a;
}

#define CP_ASYNC16(dst, src) \
    asm volatile("cp.async.cg.shared.global [%0], [%1], 16;" :: "r"(dst), "l"(src))
#define CP_COMMIT() asm volatile("cp.async.commit_group;" ::: "memory")
#define CP_WAIT1()  asm volatile("cp.async.wait_group 1;" ::: "memory")
#define CP_WAIT0()  asm volatile("cp.async.wait_group 0;" ::: "memory")

#define LDMATRIX_X4(r, addr) \
    asm volatile("ldmatrix.sync.aligned.m8n8.x4.shared.b16 {%0,%1,%2,%3}, [%4];" \
                 : "=r"((r)[0]), "=r"((r)[1]), "=r"((r)[2]), "=r"((r)[3]) : "r"(addr))
#define LDMATRIX_X4_TRANS(r, addr) \
    asm volatile("ldmatrix.sync.aligned.m8n8.x4.trans.shared.b16 {%0,%1,%2,%3}, [%4];" \
                 : "=r"((r)[0]), "=r"((r)[1]), "=r"((r)[2]), "=r"((r)[3]) : "r"(addr))

#define MMA16816(c, a, b) \
    asm volatile("mma.sync.aligned.m16n8k16.row.col.f32.bf16.bf16.f32 " \
                 "{%0,%1,%2,%3},{%4,%5,%6,%7},{%8,%9},{%0,%1,%2,%3};" \
                 : "+f"((c)[0]), "+f"((c)[1]), "+f"((c)[2]), "+f"((c)[3]) \
                 : "r"((a)[0]), "r"((a)[1]), "r"((a)[2]), "r"((a)[3]), \
                   "r"((b)[0]), "r"((b)[1]))

__device__ __forceinline__ uint32_t pack_bf16x2(float a, float b) {
    __nv_bfloat162 t = __floats2bfloat162_rn(a, b);
    return *reinterpret_cast<uint32_t*>(&t);
}

// ---------------- prepass ----------------
__global__ __launch_bounds__(256) void split_kernel(
    const float* __restrict__ in, __nv_bfloat16* __restrict__ hi,
    __nv_bfloat16* __restrict__ lo, int n)
{
    int i = blockIdx.x * 256 + threadIdx.x;
    if (i < n) {
        float v = in[i];
        __nv_bfloat16 h = __float2bfloat16(v);
        hi[i] = h;
        lo[i] = __float2bfloat16(v - __bfloat162float(h));
    }
}

__global__ __launch_bounds__(256) void tsplit_kernel(
    const float* __restrict__ in, __nv_bfloat16* __restrict__ ohi,
    __nv_bfloat16* __restrict__ olo, int R, int C)
{
    __shared__ float t[32][33];
    int c0 = blockIdx.x * 32, r0 = blockIdx.y * 32;
    int x = threadIdx.x, y = threadIdx.y;
#pragma unroll
    for (int i = 0; i < 32; i += 8)
        t[y + i][x] = in[(size_t)(r0 + y + i) * C + c0 + x];
    __syncthreads();
#pragma unroll
    for (int i = 0; i < 32; i += 8) {
        float v = t[x][y + i];
        __nv_bfloat16 h = __float2bfloat16(v);
        size_t o = (size_t)(c0 + y + i) * R + r0 + x;
        ohi[o] = h;
        olo[o] = __float2bfloat16(v - __bfloat162float(h));
    }
}

// ---------------- HMMA bf16x2 GEMM: BK=32, 3-stage, swizzled 64B rows ----------------
// Swizzle: phys_chunk = chunk ^ ((row>>1)&3); 16B chunks, 4 per 64B row.
// Conflict-free for all ldmatrix phases (verified bank-group arithmetic).
#define BM 128
#define BN 128
#define BK 32
#define ROW_B 64
#define COMP_BYTES (128 * ROW_B)       // 8192
#define STAGE_BYTES (4 * COMP_BYTES)   // 32768
#define GEMM_SMEM (3 * STAGE_BYTES)    // 98304

__global__ __launch_bounds__(256, 2) void gemm_bf16x2_kernel(
    const __nv_bfloat16* __restrict__ Ahi, const __nv_bfloat16* __restrict__ Alo,
    const __nv_bfloat16* __restrict__ Bhi, const __nv_bfloat16* __restrict__ Blo,
    const float* __restrict__ bias, float* __restrict__ C,
    __nv_bfloat16* __restrict__ Chi, __nv_bfloat16* __restrict__ Clo,
    int M, int N, int K)
{
    extern __shared__ char smem[];
    const uint32_t sbase = smem_u32(smem);
    const int tid = threadIdx.x, wid = tid >> 5, lane = tid & 31;
    const int bm = blockIdx.y * BM, bn = blockIdx.x * BN;
    const int warp_m = (wid >> 2) * 64, warp_n = (wid & 3) * 32;
    const int NT = K / BK;

    float acc[4][4][4];
#pragma unroll
    for (int i = 0; i < 4; i++)
#pragma unroll
        for (int j = 0; j < 4; j++)
#pragma unroll
            for (int r = 0; r < 4; r++) acc[i][j][r] = 0.f;

    const __nv_bfloat16* srcs[4] = {Ahi, Alo, Bhi, Blo};

    auto issue = [&](int s, int kt) {
        const uint32_t dst0 = sbase + s * STAGE_BYTES;
        const int k0 = kt * BK;
#pragma unroll
        for (int comp = 0; comp < 4; comp++) {
            const int rbase = (comp < 2) ? bm : bn;
#pragma unroll
            for (int i = 0; i < 2; i++) {
                int id = i * 256 + tid;
                int row = id >> 2, c = id & 3;
                uint32_t cc = (uint32_t)c ^ ((row >> 1) & 3);
                const __nv_bfloat16* g =
                    srcs[comp] + (size_t)(rbase + row) * K + k0 + c * 8;
                CP_ASYNC16(dst0 + comp * COMP_BYTES + row * ROW_B + cc * 16, g);
            }
        }
    };

    const int lr = lane & 15, lk = lane >> 4;
    const int brow = (lane & 7) + ((lane >> 4) << 3);
    const int bck = (lane >> 3) & 1;

    auto compute = [&](int s) {
        const uint32_t st = sbase + s * STAGE_BYTES;
#pragma unroll
        for (int ks = 0; ks < 2; ks++) {
            uint32_t bh[4][2], bl[4][2];
#pragma unroll
            for (int ntp = 0; ntp < 2; ntp++) {
                int row = warp_n + ntp * 16 + brow;
                uint32_t cidx = (uint32_t)(bck + 2 * ks) ^ ((row >> 1) & 3);
                uint32_t baddr = st + 2 * COMP_BYTES + row * ROW_B + cidx * 16;
                uint32_t r4[4];
                LDMATRIX_X4(r4, baddr);
                bh[2 * ntp][0] = r4[0]; bh[2 * ntp][1] = r4[1];
                bh[2 * ntp + 1][0] = r4[2]; bh[2 * ntp + 1][1] = r4[3];
                LDMATRIX_X4(r4, baddr + COMP_BYTES);
                bl[2 * ntp][0] = r4[0]; bl[2 * ntp][1] = r4[1];
                bl[2 * ntp + 1][0] = r4[2]; bl[2 * ntp + 1][1] = r4[3];
            }
#pragma unroll
            for (int mt = 0; mt < 4; mt++) {
                int row = warp_m + mt * 16 + lr;
                uint32_t cidx = (uint32_t)(lk + 2 * ks) ^ ((row >> 1) & 3);
                uint32_t aaddr = st + row * ROW_B + cidx * 16;
                uint32_t ah[4], al[4];
                LDMATRIX_X4(ah, aaddr);
                LDMATRIX_X4(al, aaddr + COMP_BYTES);
#pragma unroll
                for (int nt = 0; nt < 4; nt++) {
                    MMA16816(acc[mt][nt], ah, bh[nt]);
                    MMA16816(acc[mt][nt], ah, bl[nt]);
                    MMA16816(acc[mt][nt], al, bh[nt]);
                }
            }
        }
    };

    // Prologue: 2 tiles in flight
    issue(0, 0); CP_COMMIT();
    issue(1, 1); CP_COMMIT();

    int s_kt = 0, s_nx = 2;   // stage of kt, stage of kt+2
    for (int kt = 0; kt < NT; kt++) {
        CP_WAIT1();            // tile kt resident (kt+1 may be in flight)
        __syncthreads();       // everyone done reading stage s_nx (from iter kt-1)
        if (kt + 2 < NT) { issue(s_nx, kt + 2); CP_COMMIT(); }
        compute(s_kt);
        s_kt = (s_kt == 2) ? 0 : s_kt + 1;
        s_nx = (s_nx == 2) ? 0 : s_nx + 1;
    }

#pragma unroll
    for (int mt = 0; mt < 4; mt++) {
        int row0 = bm + warp_m + mt * 16 + (lane >> 2);
#pragma unroll
        for (int nt = 0; nt < 4; nt++) {
            int col = bn + warp_n + nt * 8 + 2 * (lane & 3);
            if (Chi) {
#pragma unroll
                for (int half = 0; half < 2; half++) {
                    float v0 = acc[mt][nt][2 * half];
                    float v1 = acc[mt][nt][2 * half + 1];
                    __nv_bfloat16 h0 = __float2bfloat16(v0);
                    __nv_bfloat16 h1 = __float2bfloat16(v1);
                    __nv_bfloat162 hp; hp.x = h0; hp.y = h1;
                    __nv_bfloat162 lp;
                    lp.x = __float2bfloat16(v0 - __bfloat162float(h0));
                    lp.y = __float2bfloat16(v1 - __bfloat162float(h1));
                    size_t o = (size_t)(row0 + half * 8) * N + col;
                    *reinterpret_cast<__nv_bfloat162*>(&Chi[o]) = hp;
                    *reinterpret_cast<__nv_bfloat162*>(&Clo[o]) = lp;
                }
            } else {
                float b0 = 0.f, b1 = 0.f;
                if (bias) { b0 = bias[col]; b1 = bias[col + 1]; }
                float2 v0 = make_float2(acc[mt][nt][0] + b0, acc[mt][nt][1] + b1);
                float2 v1 = make_float2(acc[mt][nt][2] + b0, acc[mt][nt][3] + b1);
                *reinterpret_cast<float2*>(&C[(size_t)row0 * N + col]) = v0;
                *reinterpret_cast<float2*>(&C[(size_t)(row0 + 8) * N + col]) = v1;
            }
        }
    }
}

// ---------------- FlashAttention-style fused attention (R5-proven, MQ=32) ----------------
#define AT_V    36864
#define AT_Q    73728
#define AT_REL  82944
#define AT_RS   83968
#define ATTN_SMEM 84480
#define AT_P4   0

__global__ __launch_bounds__(256, 2) void attn_flash_kernel(const float* __restrict__ rel_emb)
{
    extern __shared__ char smc[];
    const uint32_t sb = smem_u32(smc);
    float* Rel = (float*)(smc + AT_REL);
    float* RS  = (float*)(smc + AT_RS);
    float* P4  = (float*)(smc + AT_P4);

    const int tid = threadIdx.x, wid = tid >> 5, lane = tid & 31;
    const int pair = blockIdx.y, bt = pair >> 4, h = pair & 15;
    const int q0 = blockIdx.x * 32;
    const int wm = wid >> 2, wn = wid & 3;
    const int gr = lane >> 2, gc = lane & 3;
    const int lr = lane & 15, lk = lane >> 4;
    const int xrow = (lane & 7) + ((lane >> 4) << 3);
    const int xsel = ((lane >> 3) & 1) << 4;

    const __nv_bfloat16* ghi = g_qkv_hi + (size_t)bt * 512 * 3072 + h * 64;
    const __nv_bfloat16* glo = g_qkv_lo + (size_t)bt * 512 * 3072 + h * 64;

    auto issue_kv = [&](int t) {
#pragma unroll
        for (int i = 0; i < 18; i++) {
            int c = i * 256 + tid;
            int sec = c / 1152, rem = c - sec * 1152;
            int row = rem / 9, ch = rem - row * 9;
            const __nv_bfloat16* base = (sec & 1) ? glo : ghi;
            int comp_off = (sec < 2) ? 1024 : 2048;
            const __nv_bfloat16* src =
                base + (size_t)(t * 128 + row) * 3072 + comp_off + ch * 8;
            CP_ASYNC16(sb + sec * 18432 + row * 144 + ch * 16, src);
        }
    };

    issue_kv(0); CP_COMMIT();

    {
        __nv_bfloat16* Qh = (__nv_bfloat16*)(smc + AT_Q);
        __nv_bfloat16* Ql = (__nv_bfloat16*)(smc + AT_Q + 4608);
        for (int idx = tid; idx < 2048; idx += 256) {
            int i = idx >> 6, d = idx & 63;
            size_t g = (size_t)(q0 + i) * 3072 + d;
            Qh[i * 72 + d] = __float2bfloat16(0.125f * __bfloat162float(ghi[g]));
            Ql[i * 72 + d] = __float2bfloat16(0.125f * __bfloat162float(glo[g]));
        }
        if (tid < 255) Rel[tid] = rel_emb[tid * N_HEADS + h];
    }
    CP_WAIT0();
    __syncthreads();

    uint32_t qh[4][4], ql[4][4];
    {
        uint32_t qa = sb + AT_Q + (wm * 16 + lr) * 144 + lk * 16;
#pragma unroll
        for (int ks = 0; ks < 4; ks++) {
            LDMATRIX_X4(qh[ks], qa + ks * 32);
            LDMATRIX_X4(ql[ks], qa + 4608 + ks * 32);
        }
    }

    float o[8][4];
#pragma unroll
    for (int n = 0; n < 8; n++)
#pragma unroll
        for (int r = 0; r < 4; r++) o[n][r] = 0.f;
    float sum0 = 0.f, sum1 = 0.f;

    for (int t = 0; t < 4; t++) {
        if (t > 0) {
            issue_kv(t); CP_COMMIT();
            CP_WAIT0();
            __syncthreads();
        }

        float acc[4][4];
#pragma unroll
        for (int nt = 0; nt < 4; nt++)
#pragma unroll
            for (int r = 0; r < 4; r++) acc[nt][r] = 0.f;

#pragma unroll
        for (int ks = 0; ks < 4; ks++) {
            uint32_t bh[4][2], bl[4][2];
#pragma unroll
            for (int ntp = 0; ntp < 2; ntp++) {
                uint32_t baddr = sb + (wn * 32 + ntp * 16 + xrow) * 144 + xsel + ks * 32;
                uint32_t r4[4];
                LDMATRIX_X4(r4, baddr);
                bh[2 * ntp][0] = r4[0]; bh[2 * ntp][1] = r4[1];
                bh[2 * ntp + 1][0] = r4[2]; bh[2 * ntp + 1][1] = r4[3];
                LDMATRIX_X4(r4, baddr + 18432);
                bl[2 * ntp][0] = r4[0]; bl[2 * ntp][1] = r4[1];
                bl[2 * ntp + 1][0] = r4[2]; bl[2 * ntp + 1][1] = r4[3];
            }
#pragma unroll
            for (int nt = 0; nt < 4; nt++) {
                MMA16816(acc[nt], qh[ks], bh[nt]);
                MMA16816(acc[nt], qh[ks], bl[nt]);
                MMA16816(acc[nt], ql[ks], bh[nt]);
            }
        }

        uint32_t pfh[2][4], pfl[2][4];
#pragma unroll
        for (int nt = 0; nt < 4; nt++) {
            int gs = t * 128 + wn * 32 + nt * 8 + 2 * gc;
            int gq0 = q0 + wm * 16 + gr, gq1 = gq0 + 8;
            float e00 = __expf(acc[nt][0] + Rel[min(max(gq0 - gs,     -127), 127) + 127]);
            float e01 = __expf(acc[nt][1] + Rel[min(max(gq0 - gs - 1, -127), 127) + 127]);
            float e10 = __expf(acc[nt][2] + Rel[min(max(gq1 - gs,     -127), 127) + 127]);
            float e11 = __expf(acc[nt][3] + Rel[min(max(gq1 - gs - 1, -127), 127) + 127]);
            sum0 += e00 + e01;
            sum1 += e10 + e11;
            __nv_bfloat162 h0 = __floats2bfloat162_rn(e00, e01);
            __nv_bfloat162 h1 = __floats2bfloat162_rn(e10, e11);
            uint32_t ph0 = *reinterpret_cast<uint32_t*>(&h0);
            uint32_t ph1 = *reinterpret_cast<uint32_t*>(&h1);
            uint32_t pl0 = pack_bf16x2(e00 - __bfloat162float(h0.x), e01 - __bfloat162float(h0.y));
            uint32_t pl1 = pack_bf16x2(e10 - __bfloat162float(h1.x), e11 - __bfloat162float(h1.y));
            int kc = nt >> 1, hi2 = (nt & 1) << 1;
            pfh[kc][hi2] = ph0; pfh[kc][hi2 + 1] = ph1;
            pfl[kc][hi2] = pl0; pfl[kc][hi2 + 1] = pl1;
        }

#pragma unroll
        for (int kc = 0; kc < 2; kc++) {
#pragma unroll
            for (int dp = 0; dp < 4; dp++) {
                uint32_t va = sb + AT_V +
                    (wn * 32 + kc * 16 + (lane & 7) + (((lane >> 3) & 1) << 3)) * 144 +
                    (dp * 16 + ((lane >> 4) << 3)) * 2;
                uint32_t r4[4];
                LDMATRIX_X4_TRANS(r4, va);
                uint32_t vh0[2] = {r4[0], r4[1]}, vh1[2] = {r4[2], r4[3]};
                LDMATRIX_X4_TRANS(r4, va + 18432);
                uint32_t vl0[2] = {r4[0], r4[1]}, vl1[2] = {r4[2], r4[3]};
                MMA16816(o[2 * dp],     pfh[kc], vh0);
                MMA16816(o[2 * dp],     pfh[kc], vl0);
                MMA16816(o[2 * dp],     pfl[kc], vh0);
                MMA16816(o[2 * dp + 1], pfh[kc], vh1);
                MMA16816(o[2 * dp + 1], pfh[kc], vl1);
                MMA16816(o[2 * dp + 1], pfl[kc], vh1);
            }
        }
        __syncthreads();
    }

    sum0 += __shfl_xor_sync(0xffffffffu, sum0, 1);
    sum0 += __shfl_xor_sync(0xffffffffu, sum0, 2);
    sum1 += __shfl_xor_sync(0xffffffffu, sum1, 1);
    sum1 += __shfl_xor_sync(0xffffffffu, sum1, 2);
    if (gc == 0) {
        RS[wn * 32 + wm * 16 + gr] = sum0;
        RS[wn * 32 + wm * 16 + gr + 8] = sum1;
    }
#pragma unroll
    for (int nt = 0; nt < 8; nt++) {
        int d = nt * 8 + 2 * gc;
        int r0 = wm * 16 + gr;
        *reinterpret_cast<float2*>(&P4[(wn * 32 + r0) * 68 + d]) =
            make_float2(o[nt][0], o[nt][1]);
        *reinterpret_cast<float2*>(&P4[(wn * 32 + r0 + 8) * 68 + d]) =
            make_float2(o[nt][2], o[nt][3]);
    }
    __syncthreads();

    {
        int i0 = tid * 8;
        int r = i0 >> 6, d0 = i0 & 63;
        float inv = 1.f / (RS[r] + RS[32 + r] + RS[64 + r] + RS[96 + r]);
        size_t row = (size_t)bt * 512 + q0 + r;
        size_t ob = row * 1024 + h * 64 + d0;
#pragma unroll
        for (int j = 0; j < 8; j += 2) {
            float v0 = (P4[r * 68 + d0 + j] + P4[(32 + r) * 68 + d0 + j] +
                        P4[(64 + r) * 68 + d0 + j] + P4[(96 + r) * 68 + d0 + j]) * inv;
            float v1 = (P4[r * 68 + d0 + j + 1] + P4[(32 + r) * 68 + d0 + j + 1] +
                        P4[(64 + r) * 68 + d0 + j + 1] + P4[(96 + r) * 68 + d0 + j + 1]) * inv;
            __nv_bfloat16 h0 = __float2bfloat16(v0);
            __nv_bfloat16 h1 = __float2bfloat16(v1);
            __nv_bfloat162 hp; hp.x = h0; hp.y = h1;
            __nv_bfloat162 lp;
            lp.x = __float2bfloat16(v0 - __bfloat162float(h0));
            lp.y = __float2bfloat16(v1 - __bfloat162float(h1));
            *reinterpret_cast<__nv_bfloat162*>(&g_attn_hi[ob + j]) = hp;
            *reinterpret_cast<__nv_bfloat162*>(&g_attn_lo[ob + j]) = lp;
        }
    }
}

// ---------------- launch ----------------
extern "C" void kernel_launch(void* const* d_in, const int* in_sizes, int n_in,
                              void* d_out, int out_size)
{
    const float* x       = (const float*)d_in[0];
    const float* w_qkv   = (const float*)d_in[1];
    const float* rel_emb = (const float*)d_in[2];
    const float* w_out   = (const float*)d_in[3];
    const float* b_out   = (const float*)d_in[4];
    float* out = (float*)d_out;

    __nv_bfloat16 *xh, *xl, *wqh, *wql, *woh, *wol, *qh, *ql, *ah, *al;
    cudaGetSymbolAddress((void**)&xh, g_x_hi);
    cudaGetSymbolAddress((void**)&xl, g_x_lo);
    cudaGetSymbolAddress((void**)&wqh, g_wqkvT_hi);
    cudaGetSymbolAddress((void**)&wql, g_wqkvT_lo);
    cudaGetSymbolAddress((void**)&woh, g_woutT_hi);
    cudaGetSymbolAddress((void**)&wol, g_woutT_lo);
    cudaGetSymbolAddress((void**)&qh, g_qkv_hi);
    cudaGetSymbolAddress((void**)&ql, g_qkv_lo);
    cudaGetSymbolAddress((void**)&ah, g_attn_hi);
    cudaGetSymbolAddress((void**)&al, g_attn_lo);

    cudaFuncSetAttribute(attn_flash_kernel, cudaFuncAttributeMaxDynamicSharedMemorySize, ATTN_SMEM);
    cudaFuncSetAttribute(gemm_bf16x2_kernel, cudaFuncAttributeMaxDynamicSharedMemorySize, GEMM_SMEM);

    const int nx = 8192 * 1024;
    split_kernel<<<(nx + 255) / 256, 256>>>(x, xh, xl, nx);
    tsplit_kernel<<<dim3(3072 / 32, 1024 / 32), dim3(32, 8)>>>(w_qkv, wqh, wql, 1024, 3072);
    tsplit_kernel<<<dim3(1024 / 32, 1024 / 32), dim3(32, 8)>>>(w_out, woh, wol, 1024, 1024);

    gemm_bf16x2_kernel<<<dim3(3072 / BN, 8192 / BM), 256, GEMM_SMEM>>>(
        xh, xl, wqh, wql, nullptr, nullptr, qh, ql, 8192, 3072, 1024);

    attn_flash_kernel<<<dim3(L_SEQ / 32, 16 * N_HEADS), 256, ATTN_SMEM>>>(rel_emb);

    gemm_bf16x2_kernel<<<dim3(1024 / BN, 8192 / BM), 256, GEMM_SMEM>>>(
        ah, al, woh, wol, b_out, out, nullptr, nullptr, 8192, 1024, 1024);
}

// round 9
// speedup vs baseline: 1.2444x; 1.0076x over previous
#include <cuda_runtime.h>
#include <cuda_bf16.h>
#include <cstdint>

#define L_SEQ 512
#define D_MODEL 1024
#define N_HEADS 16

// ---------------- scratch (__device__ globals) ----------------
__device__ __nv_bfloat16 g_x_hi[(size_t)8192 * 1024];
__device__ __nv_bfloat16 g_x_lo[(size_t)8192 * 1024];
__device__ __nv_bfloat16 g_wqkvT_hi[(size_t)3072 * 1024];
__device__ __nv_bfloat16 g_wqkvT_lo[(size_t)3072 * 1024];
__device__ __nv_bfloat16 g_woutT_hi[(size_t)1024 * 1024];
__device__ __nv_bfloat16 g_woutT_lo[(size_t)1024 * 1024];
__device__ __nv_bfloat16 g_qkv_hi[(size_t)8192 * 3072];
__device__ __nv_bfloat16 g_qkv_lo[(size_t)8192 * 3072];
__device__ __nv_bfloat16 g_attn_hi[(size_t)8192 * 1024];
__device__ __nv_bfloat16 g_attn_lo[(size_t)8192 * 1024];

// ---------------- PTX helpers ----------------
__device__ __forceinline__ uint32_t smem_u32(const void* p) {
    uint32_t a;
    asm("{ .reg .u64 t; cvta.to.shared.u64 t, %1; cvt.u32.u64 %0, t; }" : "=r"(a) : "l"(p));
    return a;
}

#define CP_ASYNC16(dst, src) \
    asm volatile("cp.async.cg.shared.global [%0], [%1], 16;" :: "r"(dst), "l"(src))
#define CP_COMMIT() asm volatile("cp.async.commit_group;" ::: "memory")
#define CP_WAIT1()  asm volatile("cp.async.wait_group 1;" ::: "memory")
#define CP_WAIT0()  asm volatile("cp.async.wait_group 0;" ::: "memory")

#define LDMATRIX_X4(r, addr) \
    asm volatile("ldmatrix.sync.aligned.m8n8.x4.shared.b16 {%0,%1,%2,%3}, [%4];" \
                 : "=r"((r)[0]), "=r"((r)[1]), "=r"((r)[2]), "=r"((r)[3]) : "r"(addr))
#define LDMATRIX_X4_TRANS(r, addr) \
    asm volatile("ldmatrix.sync.aligned.m8n8.x4.trans.shared.b16 {%0,%1,%2,%3}, [%4];" \
                 : "=r"((r)[0]), "=r"((r)[1]), "=r"((r)[2]), "=r"((r)[3]) : "r"(addr))

#define MMA16816(c, a, b) \
    asm volatile("mma.sync.aligned.m16n8k16.row.col.f32.bf16.bf16.f32 " \
                 "{%0,%1,%2,%3},{%4,%5,%6,%7},{%8,%9},{%0,%1,%2,%3};" \
                 : "+f"((c)[0]), "+f"((c)[1]), "+f"((c)[2]), "+f"((c)[3]) \
                 : "r"((a)[0]), "r"((a)[1]), "r"((a)[2]), "r"((a)[3]), \
                   "r"((b)[0]), "r"((b)[1]))

__device__ __forceinline__ uint32_t pack_bf16x2(float a, float b) {
    __nv_bfloat162 t = __floats2bfloat162_rn(a, b);
    return *reinterpret_cast<uint32_t*>(&t);
}

// ---------------- prepass ----------------
__global__ __launch_bounds__(256) void split_kernel(
    const float* __restrict__ in, __nv_bfloat16* __restrict__ hi,
    __nv_bfloat16* __restrict__ lo, int n)
{
    int i = blockIdx.x * 256 + threadIdx.x;
    if (i < n) {
        float v = in[i];
        __nv_bfloat16 h = __float2bfloat16(v);
        hi[i] = h;
        lo[i] = __float2bfloat16(v - __bfloat162float(h));
    }
}

__global__ __launch_bounds__(256) void tsplit_kernel(
    const float* __restrict__ in, __nv_bfloat16* __restrict__ ohi,
    __nv_bfloat16* __restrict__ olo, int R, int C)
{
    __shared__ float t[32][33];
    int c0 = blockIdx.x * 32, r0 = blockIdx.y * 32;
    int x = threadIdx.x, y = threadIdx.y;
#pragma unroll
    for (int i = 0; i < 32; i += 8)
        t[y + i][x] = in[(size_t)(r0 + y + i) * C + c0 + x];
    __syncthreads();
#pragma unroll
    for (int i = 0; i < 32; i += 8) {
        float v = t[x][y + i];
        __nv_bfloat16 h = __float2bfloat16(v);
        size_t o = (size_t)(c0 + y + i) * R + r0 + x;
        ohi[o] = h;
        olo[o] = __float2bfloat16(v - __bfloat162float(h));
    }
}

// ---------------- HMMA bf16x2 GEMM: BK=32, 3-stage, swizzled 64B rows ----------------
#define BM 128
#define BN 128
#define BK 32
#define ROW_B 64
#define COMP_BYTES (128 * ROW_B)       // 8192
#define STAGE_BYTES (4 * COMP_BYTES)   // 32768
#define GEMM_SMEM (3 * STAGE_BYTES)    // 98304

__global__ __launch_bounds__(256, 2) void gemm_bf16x2_kernel(
    const __nv_bfloat16* __restrict__ Ahi, const __nv_bfloat16* __restrict__ Alo,
    const __nv_bfloat16* __restrict__ Bhi, const __nv_bfloat16* __restrict__ Blo,
    const float* __restrict__ bias, float* __restrict__ C,
    __nv_bfloat16* __restrict__ Chi, __nv_bfloat16* __restrict__ Clo,
    int M, int N, int K)
{
    extern __shared__ char smem[];
    const uint32_t sbase = smem_u32(smem);
    const int tid = threadIdx.x, wid = tid >> 5, lane = tid & 31;
    const int bm = blockIdx.y * BM, bn = blockIdx.x * BN;
    const int warp_m = (wid >> 2) * 64, warp_n = (wid & 3) * 32;
    const int NT = K / BK;

    float acc[4][4][4];
#pragma unroll
    for (int i = 0; i < 4; i++)
#pragma unroll
        for (int j = 0; j < 4; j++)
#pragma unroll
            for (int r = 0; r < 4; r++) acc[i][j][r] = 0.f;

    const __nv_bfloat16* srcs[4] = {Ahi, Alo, Bhi, Blo};

    auto issue = [&](int s, int kt) {
        const uint32_t dst0 = sbase + s * STAGE_BYTES;
        const int k0 = kt * BK;
#pragma unroll
        for (int comp = 0; comp < 4; comp++) {
            const int rbase = (comp < 2) ? bm : bn;
#pragma unroll
            for (int i = 0; i < 2; i++) {
                int id = i * 256 + tid;
                int row = id >> 2, c = id & 3;
                uint32_t cc = (uint32_t)c ^ ((row >> 1) & 3);
                const __nv_bfloat16* g =
                    srcs[comp] + (size_t)(rbase + row) * K + k0 + c * 8;
                CP_ASYNC16(dst0 + comp * COMP_BYTES + row * ROW_B + cc * 16, g);
            }
        }
    };

    const int lr = lane & 15, lk = lane >> 4;
    const int brow = (lane & 7) + ((lane >> 4) << 3);
    const int bck = (lane >> 3) & 1;

    auto compute = [&](int s) {
        const uint32_t st = sbase + s * STAGE_BYTES;
#pragma unroll
        for (int ks = 0; ks < 2; ks++) {
            uint32_t bh[4][2], bl[4][2];
#pragma unroll
            for (int ntp = 0; ntp < 2; ntp++) {
                int row = warp_n + ntp * 16 + brow;
                uint32_t cidx = (uint32_t)(bck + 2 * ks) ^ ((row >> 1) & 3);
                uint32_t baddr = st + 2 * COMP_BYTES + row * ROW_B + cidx * 16;
                uint32_t r4[4];
                LDMATRIX_X4(r4, baddr);
                bh[2 * ntp][0] = r4[0]; bh[2 * ntp][1] = r4[1];
                bh[2 * ntp + 1][0] = r4[2]; bh[2 * ntp + 1][1] = r4[3];
                LDMATRIX_X4(r4, baddr + COMP_BYTES);
                bl[2 * ntp][0] = r4[0]; bl[2 * ntp][1] = r4[1];
                bl[2 * ntp + 1][0] = r4[2]; bl[2 * ntp + 1][1] = r4[3];
            }
#pragma unroll
            for (int mt = 0; mt < 4; mt++) {
                int row = warp_m + mt * 16 + lr;
                uint32_t cidx = (uint32_t)(lk + 2 * ks) ^ ((row >> 1) & 3);
                uint32_t aaddr = st + row * ROW_B + cidx * 16;
                uint32_t ah[4], al[4];
                LDMATRIX_X4(ah, aaddr);
                LDMATRIX_X4(al, aaddr + COMP_BYTES);
#pragma unroll
                for (int nt = 0; nt < 4; nt++) {
                    MMA16816(acc[mt][nt], ah, bh[nt]);
                    MMA16816(acc[mt][nt], ah, bl[nt]);
                    MMA16816(acc[mt][nt], al, bh[nt]);
                }
            }
        }
    };

    issue(0, 0); CP_COMMIT();
    issue(1, 1); CP_COMMIT();

    int s_kt = 0, s_nx = 2;
    for (int kt = 0; kt < NT; kt++) {
        CP_WAIT1();
        __syncthreads();
        if (kt + 2 < NT) { issue(s_nx, kt + 2); CP_COMMIT(); }
        compute(s_kt);
        s_kt = (s_kt == 2) ? 0 : s_kt + 1;
        s_nx = (s_nx == 2) ? 0 : s_nx + 1;
    }

#pragma unroll
    for (int mt = 0; mt < 4; mt++) {
        int row0 = bm + warp_m + mt * 16 + (lane >> 2);
#pragma unroll
        for (int nt = 0; nt < 4; nt++) {
            int col = bn + warp_n + nt * 8 + 2 * (lane & 3);
            if (Chi) {
#pragma unroll
                for (int half = 0; half < 2; half++) {
                    float v0 = acc[mt][nt][2 * half];
                    float v1 = acc[mt][nt][2 * half + 1];
                    __nv_bfloat16 h0 = __float2bfloat16(v0);
                    __nv_bfloat16 h1 = __float2bfloat16(v1);
                    __nv_bfloat162 hp; hp.x = h0; hp.y = h1;
                    __nv_bfloat162 lp;
                    lp.x = __float2bfloat16(v0 - __bfloat162float(h0));
                    lp.y = __float2bfloat16(v1 - __bfloat162float(h1));
                    size_t o = (size_t)(row0 + half * 8) * N + col;
                    *reinterpret_cast<__nv_bfloat162*>(&Chi[o]) = hp;
                    *reinterpret_cast<__nv_bfloat162*>(&Clo[o]) = lp;
                }
            } else {
                float b0 = 0.f, b1 = 0.f;
                if (bias) { b0 = bias[col]; b1 = bias[col + 1]; }
                float2 v0 = make_float2(acc[mt][nt][0] + b0, acc[mt][nt][1] + b1);
                float2 v1 = make_float2(acc[mt][nt][2] + b0, acc[mt][nt][3] + b1);
                *reinterpret_cast<float2*>(&C[(size_t)row0 * N + col]) = v0;
                *reinterpret_cast<float2*>(&C[(size_t)(row0 + 8) * N + col]) = v1;
            }
        }
    }
}

// ---------------- FlashAttention-style fused attention, split K/V pipeline ----------------
#define AT_V    36864
#define AT_Q    73728
#define AT_REL  82944
#define AT_RS   83968
#define ATTN_SMEM 84480
#define AT_P4   0

__global__ __launch_bounds__(256, 2) void attn_flash_kernel(const float* __restrict__ rel_emb)
{
    extern __shared__ char smc[];
    const uint32_t sb = smem_u32(smc);
    float* Rel = (float*)(smc + AT_REL);
    float* RS  = (float*)(smc + AT_RS);
    float* P4  = (float*)(smc + AT_P4);

    const int tid = threadIdx.x, wid = tid >> 5, lane = tid & 31;
    const int pair = blockIdx.y, bt = pair >> 4, h = pair & 15;
    const int q0 = blockIdx.x * 32;
    const int wm = wid >> 2, wn = wid & 3;
    const int gr = lane >> 2, gc = lane & 3;
    const int lr = lane & 15, lk = lane >> 4;
    const int xrow = (lane & 7) + ((lane >> 4) << 3);
    const int xsel = ((lane >> 3) & 1) << 4;

    const __nv_bfloat16* ghi = g_qkv_hi + (size_t)bt * 512 * 3072 + h * 64;
    const __nv_bfloat16* glo = g_qkv_lo + (size_t)bt * 512 * 3072 + h * 64;

    auto issue_k = [&](int t) {
#pragma unroll
        for (int i = 0; i < 9; i++) {
            int c = i * 256 + tid;
            int sec = c / 1152, rem = c - sec * 1152;
            int row = rem / 9, ch = rem - row * 9;
            const __nv_bfloat16* base = sec ? glo : ghi;
            const __nv_bfloat16* src =
                base + (size_t)(t * 128 + row) * 3072 + 1024 + ch * 8;
            CP_ASYNC16(sb + sec * 18432 + row * 144 + ch * 16, src);
        }
    };
    auto issue_v = [&](int t) {
#pragma unroll
        for (int i = 0; i < 9; i++) {
            int c = i * 256 + tid;
            int sec = c / 1152, rem = c - sec * 1152;
            int row = rem / 9, ch = rem - row * 9;
            const __nv_bfloat16* base = sec ? glo : ghi;
            const __nv_bfloat16* src =
                base + (size_t)(t * 128 + row) * 3072 + 2048 + ch * 8;
            CP_ASYNC16(sb + AT_V + sec * 18432 + row * 144 + ch * 16, src);
        }
    };

    issue_k(0); CP_COMMIT();
    issue_v(0); CP_COMMIT();

    {
        __nv_bfloat16* Qh = (__nv_bfloat16*)(smc + AT_Q);
        __nv_bfloat16* Ql = (__nv_bfloat16*)(smc + AT_Q + 4608);
        for (int idx = tid; idx < 2048; idx += 256) {
            int i = idx >> 6, d = idx & 63;
            size_t g = (size_t)(q0 + i) * 3072 + d;
            Qh[i * 72 + d] = __float2bfloat16(0.125f * __bfloat162float(ghi[g]));
            Ql[i * 72 + d] = __float2bfloat16(0.125f * __bfloat162float(glo[g]));
        }
        if (tid < 255) Rel[tid] = rel_emb[tid * N_HEADS + h];
    }
    CP_WAIT1();        // K(0) ready; V(0) may be in flight
    __syncthreads();   // + Q/Rel visible

    uint32_t qh[4][4], ql[4][4];
    {
        uint32_t qa = sb + AT_Q + (wm * 16 + lr) * 144 + lk * 16;
#pragma unroll
        for (int ks = 0; ks < 4; ks++) {
            LDMATRIX_X4(qh[ks], qa + ks * 32);
            LDMATRIX_X4(ql[ks], qa + 4608 + ks * 32);
        }
    }

    float o[8][4];
#pragma unroll
    for (int n = 0; n < 8; n++)
#pragma unroll
        for (int r = 0; r < 4; r++) o[n][r] = 0.f;
    float sum0 = 0.f, sum1 = 0.f;

    for (int t = 0; t < 4; t++) {
        // ---- QK(t): reads K buffer ----
        float acc[4][4];
#pragma unroll
        for (int nt = 0; nt < 4; nt++)
#pragma unroll
            for (int r = 0; r < 4; r++) acc[nt][r] = 0.f;

#pragma unroll
        for (int ks = 0; ks < 4; ks++) {
            uint32_t bh[4][2], bl[4][2];
#pragma unroll
            for (int ntp = 0; ntp < 2; ntp++) {
                uint32_t baddr = sb + (wn * 32 + ntp * 16 + xrow) * 144 + xsel + ks * 32;
                uint32_t r4[4];
                LDMATRIX_X4(r4, baddr);
                bh[2 * ntp][0] = r4[0]; bh[2 * ntp][1] = r4[1];
                bh[2 * ntp + 1][0] = r4[2]; bh[2 * ntp + 1][1] = r4[3];
                LDMATRIX_X4(r4, baddr + 18432);
                bl[2 * ntp][0] = r4[0]; bl[2 * ntp][1] = r4[1];
                bl[2 * ntp + 1][0] = r4[2]; bl[2 * ntp + 1][1] = r4[3];
            }
#pragma unroll
            for (int nt = 0; nt < 4; nt++) {
                MMA16816(acc[nt], qh[ks], bh[nt]);
                MMA16816(acc[nt], qh[ks], bl[nt]);
                MMA16816(acc[nt], ql[ks], bh[nt]);
            }
        }

        __syncthreads();                               // K readers done
        if (t < 3) { issue_k(t + 1); CP_COMMIT(); }    // overlaps exp + PV(t)

        // ---- exp/P in registers ----
        uint32_t pfh[2][4], pfl[2][4];
#pragma unroll
        for (int nt = 0; nt < 4; nt++) {
            int gs = t * 128 + wn * 32 + nt * 8 + 2 * gc;
            int gq0 = q0 + wm * 16 + gr, gq1 = gq0 + 8;
            float e00 = __expf(acc[nt][0] + Rel[min(max(gq0 - gs,     -127), 127) + 127]);
            float e01 = __expf(acc[nt][1] + Rel[min(max(gq0 - gs - 1, -127), 127) + 127]);
            float e10 = __expf(acc[nt][2] + Rel[min(max(gq1 - gs,     -127), 127) + 127]);
            float e11 = __expf(acc[nt][3] + Rel[min(max(gq1 - gs - 1, -127), 127) + 127]);
            sum0 += e00 + e01;
            sum1 += e10 + e11;
            __nv_bfloat162 h0 = __floats2bfloat162_rn(e00, e01);
            __nv_bfloat162 h1 = __floats2bfloat162_rn(e10, e11);
            uint32_t ph0 = *reinterpret_cast<uint32_t*>(&h0);
            uint32_t ph1 = *reinterpret_cast<uint32_t*>(&h1);
            uint32_t pl0 = pack_bf16x2(e00 - __bfloat162float(h0.x), e01 - __bfloat162float(h0.y));
            uint32_t pl1 = pack_bf16x2(e10 - __bfloat162float(h1.x), e11 - __bfloat162float(h1.y));
            int kc = nt >> 1, hi2 = (nt & 1) << 1;
            pfh[kc][hi2] = ph0; pfh[kc][hi2 + 1] = ph1;
            pfl[kc][hi2] = pl0; pfl[kc][hi2 + 1] = pl1;
        }

        // V(t) ready. t<3: outstanding={V(t),K(t+1)} -> wait1 pins V(t).
        // t==3: outstanding={V(3)} ONLY -> must drain fully (race fix).
        if (t < 3) { CP_WAIT1(); } else { CP_WAIT0(); }
        __syncthreads();

        // ---- PV(t): reads V buffer ----
#pragma unroll
        for (int kc = 0; kc < 2; kc++) {
#pragma unroll
            for (int dp = 0; dp < 4; dp++) {
                uint32_t va = sb + AT_V +
                    (wn * 32 + kc * 16 + (lane & 7) + (((lane >> 3) & 1) << 3)) * 144 +
                    (dp * 16 + ((lane >> 4) << 3)) * 2;
                uint32_t r4[4];
                LDMATRIX_X4_TRANS(r4, va);
                uint32_t vh0[2] = {r4[0], r4[1]}, vh1[2] = {r4[2], r4[3]};
                LDMATRIX_X4_TRANS(r4, va + 18432);
                uint32_t vl0[2] = {r4[0], r4[1]}, vl1[2] = {r4[2], r4[3]};
                MMA16816(o[2 * dp],     pfh[kc], vh0);
                MMA16816(o[2 * dp],     pfh[kc], vl0);
                MMA16816(o[2 * dp],     pfl[kc], vh0);
                MMA16816(o[2 * dp + 1], pfh[kc], vh1);
                MMA16816(o[2 * dp + 1], pfh[kc], vl1);
                MMA16816(o[2 * dp + 1], pfl[kc], vh1);
            }
        }

        __syncthreads();                               // V readers done
        if (t < 3) {
            issue_v(t + 1); CP_COMMIT();               // overlaps QK(t+1)
            CP_WAIT1();                                // K(t+1) ready
            __syncthreads();
        }
    }

    sum0 += __shfl_xor_sync(0xffffffffu, sum0, 1);
    sum0 += __shfl_xor_sync(0xffffffffu, sum0, 2);
    sum1 += __shfl_xor_sync(0xffffffffu, sum1, 1);
    sum1 += __shfl_xor_sync(0xffffffffu, sum1, 2);
    if (gc == 0) {
        RS[wn * 32 + wm * 16 + gr] = sum0;
        RS[wn * 32 + wm * 16 + gr + 8] = sum1;
    }
#pragma unroll
    for (int nt = 0; nt < 8; nt++) {
        int d = nt * 8 + 2 * gc;
        int r0 = wm * 16 + gr;
        *reinterpret_cast<float2*>(&P4[(wn * 32 + r0) * 68 + d]) =
            make_float2(o[nt][0], o[nt][1]);
        *reinterpret_cast<float2*>(&P4[(wn * 32 + r0 + 8) * 68 + d]) =
            make_float2(o[nt][2], o[nt][3]);
    }
    __syncthreads();

    {
        int i0 = tid * 8;
        int r = i0 >> 6, d0 = i0 & 63;
        float inv = 1.f / (RS[r] + RS[32 + r] + RS[64 + r] + RS[96 + r]);
        size_t row = (size_t)bt * 512 + q0 + r;
        size_t ob = row * 1024 + h * 64 + d0;
#pragma unroll
        for (int j = 0; j < 8; j += 2) {
            float v0 = (P4[r * 68 + d0 + j] + P4[(32 + r) * 68 + d0 + j] +
                        P4[(64 + r) * 68 + d0 + j] + P4[(96 + r) * 68 + d0 + j]) * inv;
            float v1 = (P4[r * 68 + d0 + j + 1] + P4[(32 + r) * 68 + d0 + j + 1] +
                        P4[(64 + r) * 68 + d0 + j + 1] + P4[(96 + r) * 68 + d0 + j + 1]) * inv;
            __nv_bfloat16 h0 = __float2bfloat16(v0);
            __nv_bfloat16 h1 = __float2bfloat16(v1);
            __nv_bfloat162 hp; hp.x = h0; hp.y = h1;
            __nv_bfloat162 lp;
            lp.x = __float2bfloat16(v0 - __bfloat162float(h0));
            lp.y = __float2bfloat16(v1 - __bfloat162float(h1));
            *reinterpret_cast<__nv_bfloat162*>(&g_attn_hi[ob + j]) = hp;
            *reinterpret_cast<__nv_bfloat162*>(&g_attn_lo[ob + j]) = lp;
        }
    }
}

// ---------------- launch ----------------
extern "C" void kernel_launch(void* const* d_in, const int* in_sizes, int n_in,
                              void* d_out, int out_size)
{
    const float* x       = (const float*)d_in[0];
    const float* w_qkv   = (const float*)d_in[1];
    const float* rel_emb = (const float*)d_in[2];
    const float* w_out   = (const float*)d_in[3];
    const float* b_out   = (const float*)d_in[4];
    float* out = (float*)d_out;

    __nv_bfloat16 *xh, *xl, *wqh, *wql, *woh, *wol, *qh, *ql, *ah, *al;
    cudaGetSymbolAddress((void**)&xh, g_x_hi);
    cudaGetSymbolAddress((void**)&xl, g_x_lo);
    cudaGetSymbolAddress((void**)&wqh, g_wqkvT_hi);
    cudaGetSymbolAddress((void**)&wql, g_wqkvT_lo);
    cudaGetSymbolAddress((void**)&woh, g_woutT_hi);
    cudaGetSymbolAddress((void**)&wol, g_woutT_lo);
    cudaGetSymbolAddress((void**)&qh, g_qkv_hi);
    cudaGetSymbolAddress((void**)&ql, g_qkv_lo);
    cudaGetSymbolAddress((void**)&ah, g_attn_hi);
    cudaGetSymbolAddress((void**)&al, g_attn_lo);

    cudaFuncSetAttribute(attn_flash_kernel, cudaFuncAttributeMaxDynamicSharedMemorySize, ATTN_SMEM);
    cudaFuncSetAttribute(gemm_bf16x2_kernel, cudaFuncAttributeMaxDynamicSharedMemorySize, GEMM_SMEM);

    const int nx = 8192 * 1024;
    split_kernel<<<(nx + 255) / 256, 256>>>(x, xh, xl, nx);
    tsplit_kernel<<<dim3(3072 / 32, 1024 / 32), dim3(32, 8)>>>(w_qkv, wqh, wql, 1024, 3072);
    tsplit_kernel<<<dim3(1024 / 32, 1024 / 32), dim3(32, 8)>>>(w_out, woh, wol, 1024, 1024);

    gemm_bf16x2_kernel<<<dim3(3072 / BN, 8192 / BM), 256, GEMM_SMEM>>>(
        xh, xl, wqh, wql, nullptr, nullptr, qh, ql, 8192, 3072, 1024);

    attn_flash_kernel<<<dim3(L_SEQ / 32, 16 * N_HEADS), 256, ATTN_SMEM>>>(rel_emb);

    gemm_bf16x2_kernel<<<dim3(1024 / BN, 8192 / BM), 256, GEMM_SMEM>>>(
        ah, al, woh, wol, b_out, out, nullptr, nullptr, 8192, 1024, 1024);
}

// round 10
// speedup vs baseline: 1.4282x; 1.1477x over previous
#include <cuda_runtime.h>
#include <cuda_bf16.h>
#include <cstdint>

#define L_SEQ 512
#define D_MODEL 1024
#define N_HEADS 16

// ---------------- scratch (__device__ globals) ----------------
__device__ __nv_bfloat16 g_x_hi[(size_t)8192 * 1024];
__device__ __nv_bfloat16 g_x_lo[(size_t)8192 * 1024];
__device__ __nv_bfloat16 g_wqkvT_hi[(size_t)3072 * 1024];
__device__ __nv_bfloat16 g_wqkvT_lo[(size_t)3072 * 1024];
__device__ __nv_bfloat16 g_woutT_hi[(size_t)1024 * 1024];
__device__ __nv_bfloat16 g_woutT_lo[(size_t)1024 * 1024];
__device__ __nv_bfloat16 g_qkv_hi[(size_t)8192 * 3072];
__device__ __nv_bfloat16 g_qkv_lo[(size_t)8192 * 3072];
__device__ __nv_bfloat16 g_attn_hi[(size_t)8192 * 1024];
__device__ __nv_bfloat16 g_attn_lo[(size_t)8192 * 1024];

// ---------------- PTX helpers ----------------
__device__ __forceinline__ uint32_t smem_u32(const void* p) {
    uint32_t a;
    asm("{ .reg .u64 t; cvta.to.shared.u64 t, %1; cvt.u32.u64 %0, t; }" : "=r"(a) : "l"(p));
    return a;
}

#define CP_ASYNC16(dst, src) \
    asm volatile("cp.async.cg.shared.global [%0], [%1], 16;" :: "r"(dst), "l"(src))
#define CP_COMMIT() asm volatile("cp.async.commit_group;" ::: "memory")
#define CP_WAIT1()  asm volatile("cp.async.wait_group 1;" ::: "memory")
#define CP_WAIT0()  asm volatile("cp.async.wait_group 0;" ::: "memory")

#define LDMATRIX_X4(r, addr) \
    asm volatile("ldmatrix.sync.aligned.m8n8.x4.shared.b16 {%0,%1,%2,%3}, [%4];" \
                 : "=r"((r)[0]), "=r"((r)[1]), "=r"((r)[2]), "=r"((r)[3]) : "r"(addr))
#define LDMATRIX_X4_TRANS(r, addr) \
    asm volatile("ldmatrix.sync.aligned.m8n8.x4.trans.shared.b16 {%0,%1,%2,%3}, [%4];" \
                 : "=r"((r)[0]), "=r"((r)[1]), "=r"((r)[2]), "=r"((r)[3]) : "r"(addr))

#define MMA16816(c, a, b) \
    asm volatile("mma.sync.aligned.m16n8k16.row.col.f32.bf16.bf16.f32 " \
                 "{%0,%1,%2,%3},{%4,%5,%6,%7},{%8,%9},{%0,%1,%2,%3};" \
                 : "+f"((c)[0]), "+f"((c)[1]), "+f"((c)[2]), "+f"((c)[3]) \
                 : "r"((a)[0]), "r"((a)[1]), "r"((a)[2]), "r"((a)[3]), \
                   "r"((b)[0]), "r"((b)[1]))

__device__ __forceinline__ uint32_t pack_bf16x2(float a, float b) {
    __nv_bfloat162 t = __floats2bfloat162_rn(a, b);
    return *reinterpret_cast<uint32_t*>(&t);
}

// ---------------- prepass ----------------
__global__ __launch_bounds__(256) void split_kernel(
    const float* __restrict__ in, __nv_bfloat16* __restrict__ hi,
    __nv_bfloat16* __restrict__ lo, int n)
{
    int i = blockIdx.x * 256 + threadIdx.x;
    if (i < n) {
        float v = in[i];
        __nv_bfloat16 h = __float2bfloat16(v);
        hi[i] = h;
        lo[i] = __float2bfloat16(v - __bfloat162float(h));
    }
}

__global__ __launch_bounds__(256) void tsplit_kernel(
    const float* __restrict__ in, __nv_bfloat16* __restrict__ ohi,
    __nv_bfloat16* __restrict__ olo, int R, int C)
{
    __shared__ float t[32][33];
    int c0 = blockIdx.x * 32, r0 = blockIdx.y * 32;
    int x = threadIdx.x, y = threadIdx.y;
#pragma unroll
    for (int i = 0; i < 32; i += 8)
        t[y + i][x] = in[(size_t)(r0 + y + i) * C + c0 + x];
    __syncthreads();
#pragma unroll
    for (int i = 0; i < 32; i += 8) {
        float v = t[x][y + i];
        __nv_bfloat16 h = __float2bfloat16(v);
        size_t o = (size_t)(c0 + y + i) * R + r0 + x;
        ohi[o] = h;
        olo[o] = __float2bfloat16(v - __bfloat162float(h));
    }
}

// ---------------- HMMA bf16x2 GEMM: BK=32, 3-stage, swizzled 64B rows (R7 frozen) ----------------
#define BM 128
#define BN 128
#define BK 32
#define ROW_B 64
#define COMP_BYTES (128 * ROW_B)       // 8192
#define STAGE_BYTES (4 * COMP_BYTES)   // 32768
#define GEMM_SMEM (3 * STAGE_BYTES)    // 98304

__global__ __launch_bounds__(256, 2) void gemm_bf16x2_kernel(
    const __nv_bfloat16* __restrict__ Ahi, const __nv_bfloat16* __restrict__ Alo,
    const __nv_bfloat16* __restrict__ Bhi, const __nv_bfloat16* __restrict__ Blo,
    const float* __restrict__ bias, float* __restrict__ C,
    __nv_bfloat16* __restrict__ Chi, __nv_bfloat16* __restrict__ Clo,
    int M, int N, int K)
{
    extern __shared__ char smem[];
    const uint32_t sbase = smem_u32(smem);
    const int tid = threadIdx.x, wid = tid >> 5, lane = tid & 31;
    const int bm = blockIdx.y * BM, bn = blockIdx.x * BN;
    const int warp_m = (wid >> 2) * 64, warp_n = (wid & 3) * 32;
    const int NT = K / BK;

    float acc[4][4][4];
#pragma unroll
    for (int i = 0; i < 4; i++)
#pragma unroll
        for (int j = 0; j < 4; j++)
#pragma unroll
            for (int r = 0; r < 4; r++) acc[i][j][r] = 0.f;

    const __nv_bfloat16* srcs[4] = {Ahi, Alo, Bhi, Blo};

    auto issue = [&](int s, int kt) {
        const uint32_t dst0 = sbase + s * STAGE_BYTES;
        const int k0 = kt * BK;
#pragma unroll
        for (int comp = 0; comp < 4; comp++) {
            const int rbase = (comp < 2) ? bm : bn;
#pragma unroll
            for (int i = 0; i < 2; i++) {
                int id = i * 256 + tid;
                int row = id >> 2, c = id & 3;
                uint32_t cc = (uint32_t)c ^ ((row >> 1) & 3);
                const __nv_bfloat16* g =
                    srcs[comp] + (size_t)(rbase + row) * K + k0 + c * 8;
                CP_ASYNC16(dst0 + comp * COMP_BYTES + row * ROW_B + cc * 16, g);
            }
        }
    };

    const int lr = lane & 15, lk = lane >> 4;
    const int brow = (lane & 7) + ((lane >> 4) << 3);
    const int bck = (lane >> 3) & 1;

    auto compute = [&](int s) {
        const uint32_t st = sbase + s * STAGE_BYTES;
#pragma unroll
        for (int ks = 0; ks < 2; ks++) {
            uint32_t bh[4][2], bl[4][2];
#pragma unroll
            for (int ntp = 0; ntp < 2; ntp++) {
                int row = warp_n + ntp * 16 + brow;
                uint32_t cidx = (uint32_t)(bck + 2 * ks) ^ ((row >> 1) & 3);
                uint32_t baddr = st + 2 * COMP_BYTES + row * ROW_B + cidx * 16;
                uint32_t r4[4];
                LDMATRIX_X4(r4, baddr);
                bh[2 * ntp][0] = r4[0]; bh[2 * ntp][1] = r4[1];
                bh[2 * ntp + 1][0] = r4[2]; bh[2 * ntp + 1][1] = r4[3];
                LDMATRIX_X4(r4, baddr + COMP_BYTES);
                bl[2 * ntp][0] = r4[0]; bl[2 * ntp][1] = r4[1];
                bl[2 * ntp + 1][0] = r4[2]; bl[2 * ntp + 1][1] = r4[3];
            }
#pragma unroll
            for (int mt = 0; mt < 4; mt++) {
                int row = warp_m + mt * 16 + lr;
                uint32_t cidx = (uint32_t)(lk + 2 * ks) ^ ((row >> 1) & 3);
                uint32_t aaddr = st + row * ROW_B + cidx * 16;
                uint32_t ah[4], al[4];
                LDMATRIX_X4(ah, aaddr);
                LDMATRIX_X4(al, aaddr + COMP_BYTES);
#pragma unroll
                for (int nt = 0; nt < 4; nt++) {
                    MMA16816(acc[mt][nt], ah, bh[nt]);
                    MMA16816(acc[mt][nt], ah, bl[nt]);
                    MMA16816(acc[mt][nt], al, bh[nt]);
                }
            }
        }
    };

    issue(0, 0); CP_COMMIT();
    issue(1, 1); CP_COMMIT();

    int s_kt = 0, s_nx = 2;
    for (int kt = 0; kt < NT; kt++) {
        CP_WAIT1();
        __syncthreads();
        if (kt + 2 < NT) { issue(s_nx, kt + 2); CP_COMMIT(); }
        compute(s_kt);
        s_kt = (s_kt == 2) ? 0 : s_kt + 1;
        s_nx = (s_nx == 2) ? 0 : s_nx + 1;
    }

#pragma unroll
    for (int mt = 0; mt < 4; mt++) {
        int row0 = bm + warp_m + mt * 16 + (lane >> 2);
#pragma unroll
        for (int nt = 0; nt < 4; nt++) {
            int col = bn + warp_n + nt * 8 + 2 * (lane & 3);
            if (Chi) {
#pragma unroll
                for (int half = 0; half < 2; half++) {
                    float v0 = acc[mt][nt][2 * half];
                    float v1 = acc[mt][nt][2 * half + 1];
                    __nv_bfloat16 h0 = __float2bfloat16(v0);
                    __nv_bfloat16 h1 = __float2bfloat16(v1);
                    __nv_bfloat162 hp; hp.x = h0; hp.y = h1;
                    __nv_bfloat162 lp;
                    lp.x = __float2bfloat16(v0 - __bfloat162float(h0));
                    lp.y = __float2bfloat16(v1 - __bfloat162float(h1));
                    size_t o = (size_t)(row0 + half * 8) * N + col;
                    *reinterpret_cast<__nv_bfloat162*>(&Chi[o]) = hp;
                    *reinterpret_cast<__nv_bfloat162*>(&Clo[o]) = lp;
                }
            } else {
                float b0 = 0.f, b1 = 0.f;
                if (bias) { b0 = bias[col]; b1 = bias[col + 1]; }
                float2 v0 = make_float2(acc[mt][nt][0] + b0, acc[mt][nt][1] + b1);
                float2 v1 = make_float2(acc[mt][nt][2] + b0, acc[mt][nt][3] + b1);
                *reinterpret_cast<float2*>(&C[(size_t)row0 * N + col]) = v0;
                *reinterpret_cast<float2*>(&C[(size_t)(row0 + 8) * N + col]) = v1;
            }
        }
    }
}

// ---------------- Fused attention: MQ=128, warp owns 16 queries x ALL keys ----------------
// smem: K hi|lo (36864) | V hi|lo (36864) | Q hi|lo (36864) | Rel (1024) = 111616
// 2 CTAs/SM. 2 syncs per K-tile, 384 warp-MMAs between. No cross-warp O reduction.
#define AT_V    36864
#define AT_Q    73728
#define AT_REL  110592
#define ATTN_SMEM 111616

__global__ __launch_bounds__(256, 2) void attn_flash_kernel(const float* __restrict__ rel_emb)
{
    extern __shared__ char smc[];
    const uint32_t sb = smem_u32(smc);
    float* Rel = (float*)(smc + AT_REL);

    const int tid = threadIdx.x, wid = tid >> 5, lane = tid & 31;
    const int pair = blockIdx.y, bt = pair >> 4, h = pair & 15;
    const int q0 = blockIdx.x * 128;
    const int gr = lane >> 2, gc = lane & 3;
    const int lr = lane & 15, lk = lane >> 4;
    const int xrow = (lane & 7) + ((lane >> 4) << 3);   // K ldmatrix X4 row select
    const int xsel = ((lane >> 3) & 1) << 4;            // K ldmatrix 16B select
    const int vrow = (lane & 7) + (((lane >> 3) & 1) << 3);  // V trans row select
    const int vcol = ((lane >> 4) << 3) * 2;                 // V trans byte select

    const __nv_bfloat16* ghi = g_qkv_hi + (size_t)bt * 512 * 3072 + h * 64;
    const __nv_bfloat16* glo = g_qkv_lo + (size_t)bt * 512 * 3072 + h * 64;

    // K+V loader (tile t = 128 keys): sections 0=Khi 1=Klo 2=Vhi 3=Vlo, 128x144B each
    auto issue_kv = [&](int t) {
#pragma unroll
        for (int i = 0; i < 18; i++) {
            int c = i * 256 + tid;
            int sec = c / 1152, rem = c - sec * 1152;
            int row = rem / 9, ch = rem - row * 9;
            const __nv_bfloat16* base = (sec & 1) ? glo : ghi;
            int comp_off = (sec < 2) ? 1024 : 2048;   // K : V
            const __nv_bfloat16* src =
                base + (size_t)(t * 128 + row) * 3072 + comp_off + ch * 8;
            CP_ASYNC16(sb + sec * 18432 + row * 144 + ch * 16, src);
        }
    };

    issue_kv(0); CP_COMMIT();

    // Q tile (128 rows, scale 0.125 folded — exact), Rel column
    {
        __nv_bfloat16* Qh = (__nv_bfloat16*)(smc + AT_Q);
        __nv_bfloat16* Ql = (__nv_bfloat16*)(smc + AT_Q + 18432);
        for (int idx = tid; idx < 8192; idx += 256) {
            int i = idx >> 6, d = idx & 63;
            size_t g = (size_t)(q0 + i) * 3072 + d;
            Qh[i * 72 + d] = __float2bfloat16(0.125f * __bfloat162float(ghi[g]));
            Ql[i * 72 + d] = __float2bfloat16(0.125f * __bfloat162float(glo[g]));
        }
        if (tid < 255) Rel[tid] = rel_emb[tid * N_HEADS + h];
    }
    CP_WAIT0();
    __syncthreads();

    // Q fragments: persistent (warp's 16 rows)
    uint32_t qh[4][4], ql[4][4];
    {
        uint32_t qa = sb + AT_Q + (wid * 16 + lr) * 144 + lk * 16;
#pragma unroll
        for (int ks = 0; ks < 4; ks++) {
            LDMATRIX_X4(qh[ks], qa + ks * 32);
            LDMATRIX_X4(ql[ks], qa + 18432 + ks * 32);
        }
    }

    float o[8][4];
#pragma unroll
    for (int n = 0; n < 8; n++)
#pragma unroll
        for (int r = 0; r < 4; r++) o[n][r] = 0.f;
    float sum0 = 0.f, sum1 = 0.f;

    const int gq0 = q0 + wid * 16 + gr;
    const int gq1 = gq0 + 8;

#pragma unroll 1
    for (int t = 0; t < 4; t++) {
        // kc-interleaved: per 16-key chunk: QK -> exp -> PV
#pragma unroll
        for (int kc = 0; kc < 8; kc++) {
            // ---- QK: 16 keys ----
            float acc[2][4];
#pragma unroll
            for (int j = 0; j < 2; j++)
#pragma unroll
                for (int r = 0; r < 4; r++) acc[j][r] = 0.f;

#pragma unroll
            for (int ks = 0; ks < 4; ks++) {
                uint32_t baddr = sb + (kc * 16 + xrow) * 144 + xsel + ks * 32;
                uint32_t r4[4];
                uint32_t bh0[2], bh1[2], bl0[2], bl1[2];
                LDMATRIX_X4(r4, baddr);
                bh0[0] = r4[0]; bh0[1] = r4[1]; bh1[0] = r4[2]; bh1[1] = r4[3];
                LDMATRIX_X4(r4, baddr + 18432);
                bl0[0] = r4[0]; bl0[1] = r4[1]; bl1[0] = r4[2]; bl1[1] = r4[3];
                MMA16816(acc[0], qh[ks], bh0);
                MMA16816(acc[0], qh[ks], bl0);
                MMA16816(acc[0], ql[ks], bh0);
                MMA16816(acc[1], qh[ks], bh1);
                MMA16816(acc[1], qh[ks], bl1);
                MMA16816(acc[1], ql[ks], bh1);
            }

            // ---- bias + exp + running sums + P frags ----
            uint32_t pfh[4], pfl[4];
#pragma unroll
            for (int j = 0; j < 2; j++) {
                int gs = t * 128 + kc * 16 + j * 8 + 2 * gc;
                float e00 = __expf(acc[j][0] + Rel[min(max(gq0 - gs,     -127), 127) + 127]);
                float e01 = __expf(acc[j][1] + Rel[min(max(gq0 - gs - 1, -127), 127) + 127]);
                float e10 = __expf(acc[j][2] + Rel[min(max(gq1 - gs,     -127), 127) + 127]);
                float e11 = __expf(acc[j][3] + Rel[min(max(gq1 - gs - 1, -127), 127) + 127]);
                sum0 += e00 + e01;
                sum1 += e10 + e11;
                __nv_bfloat162 h0 = __floats2bfloat162_rn(e00, e01);
                __nv_bfloat162 h1 = __floats2bfloat162_rn(e10, e11);
                pfh[2 * j]     = *reinterpret_cast<uint32_t*>(&h0);
                pfh[2 * j + 1] = *reinterpret_cast<uint32_t*>(&h1);
                pfl[2 * j]     = pack_bf16x2(e00 - __bfloat162float(h0.x),
                                             e01 - __bfloat162float(h0.y));
                pfl[2 * j + 1] = pack_bf16x2(e10 - __bfloat162float(h1.x),
                                             e11 - __bfloat162float(h1.y));
            }

            // ---- PV: same 16 keys into O ----
#pragma unroll
            for (int dp = 0; dp < 4; dp++) {
                uint32_t va = sb + AT_V + (kc * 16 + vrow) * 144 + dp * 32 + vcol;
                uint32_t r4[4];
                uint32_t vh0[2], vh1[2], vl0[2], vl1[2];
                LDMATRIX_X4_TRANS(r4, va);
                vh0[0] = r4[0]; vh0[1] = r4[1]; vh1[0] = r4[2]; vh1[1] = r4[3];
                LDMATRIX_X4_TRANS(r4, va + 18432);
                vl0[0] = r4[0]; vl0[1] = r4[1]; vl1[0] = r4[2]; vl1[1] = r4[3];
                MMA16816(o[2 * dp],     pfh, vh0);
                MMA16816(o[2 * dp],     pfh, vl0);
                MMA16816(o[2 * dp],     pfl, vh0);
                MMA16816(o[2 * dp + 1], pfh, vh1);
                MMA16816(o[2 * dp + 1], pfh, vl1);
                MMA16816(o[2 * dp + 1], pfl, vh1);
            }
        }

        if (t < 3) {
            __syncthreads();                 // all readers done with K/V tile t
            issue_kv(t + 1); CP_COMMIT();
            CP_WAIT0();                      // drain own copies (deterministic)
            __syncthreads();                 // all threads' copies visible
        }
    }

    // ---- normalize + split-store O (no cross-warp reduction needed) ----
    sum0 += __shfl_xor_sync(0xffffffffu, sum0, 1);
    sum0 += __shfl_xor_sync(0xffffffffu, sum0, 2);
    sum1 += __shfl_xor_sync(0xffffffffu, sum1, 1);
    sum1 += __shfl_xor_sync(0xffffffffu, sum1, 2);
    float inv0 = 1.f / sum0, inv1 = 1.f / sum1;

    size_t row0 = (size_t)bt * 512 + gq0;    // = bt*512 + q0 + wid*16 + gr
#pragma unroll
    for (int nt = 0; nt < 8; nt++) {
        int col = h * 64 + nt * 8 + 2 * gc;
        float v0 = o[nt][0] * inv0, v1 = o[nt][1] * inv0;
        float v2 = o[nt][2] * inv1, v3 = o[nt][3] * inv1;
        __nv_bfloat16 a0 = __float2bfloat16(v0), a1 = __float2bfloat16(v1);
        __nv_bfloat16 b0 = __float2bfloat16(v2), b1 = __float2bfloat16(v3);
        __nv_bfloat162 hp0; hp0.x = a0; hp0.y = a1;
        __nv_bfloat162 hp1; hp1.x = b0; hp1.y = b1;
        __nv_bfloat162 lp0;
        lp0.x = __float2bfloat16(v0 - __bfloat162float(a0));
        lp0.y = __float2bfloat16(v1 - __bfloat162float(a1));
        __nv_bfloat162 lp1;
        lp1.x = __float2bfloat16(v2 - __bfloat162float(b0));
        lp1.y = __float2bfloat16(v3 - __bfloat162float(b1));
        *reinterpret_cast<__nv_bfloat162*>(&g_attn_hi[row0 * 1024 + col]) = hp0;
        *reinterpret_cast<__nv_bfloat162*>(&g_attn_lo[row0 * 1024 + col]) = lp0;
        *reinterpret_cast<__nv_bfloat162*>(&g_attn_hi[(row0 + 8) * 1024 + col]) = hp1;
        *reinterpret_cast<__nv_bfloat162*>(&g_attn_lo[(row0 + 8) * 1024 + col]) = lp1;
    }
}

// ---------------- launch ----------------
extern "C" void kernel_launch(void* const* d_in, const int* in_sizes, int n_in,
                              void* d_out, int out_size)
{
    const float* x       = (const float*)d_in[0];
    const float* w_qkv   = (const float*)d_in[1];
    const float* rel_emb = (const float*)d_in[2];
    const float* w_out   = (const float*)d_in[3];
    const float* b_out   = (const float*)d_in[4];
    float* out = (float*)d_out;

    __nv_bfloat16 *xh, *xl, *wqh, *wql, *woh, *wol, *qh, *ql, *ah, *al;
    cudaGetSymbolAddress((void**)&xh, g_x_hi);
    cudaGetSymbolAddress((void**)&xl, g_x_lo);
    cudaGetSymbolAddress((void**)&wqh, g_wqkvT_hi);
    cudaGetSymbolAddress((void**)&wql, g_wqkvT_lo);
    cudaGetSymbolAddress((void**)&woh, g_woutT_hi);
    cudaGetSymbolAddress((void**)&wol, g_woutT_lo);
    cudaGetSymbolAddress((void**)&qh, g_qkv_hi);
    cudaGetSymbolAddress((void**)&ql, g_qkv_lo);
    cudaGetSymbolAddress((void**)&ah, g_attn_hi);
    cudaGetSymbolAddress((void**)&al, g_attn_lo);

    cudaFuncSetAttribute(attn_flash_kernel, cudaFuncAttributeMaxDynamicSharedMemorySize, ATTN_SMEM);
    cudaFuncSetAttribute(gemm_bf16x2_kernel, cudaFuncAttributeMaxDynamicSharedMemorySize, GEMM_SMEM);

    const int nx = 8192 * 1024;
    split_kernel<<<(nx + 255) / 256, 256>>>(x, xh, xl, nx);
    tsplit_kernel<<<dim3(3072 / 32, 1024 / 32), dim3(32, 8)>>>(w_qkv, wqh, wql, 1024, 3072);
    tsplit_kernel<<<dim3(1024 / 32, 1024 / 32), dim3(32, 8)>>>(w_out, woh, wol, 1024, 1024);

    gemm_bf16x2_kernel<<<dim3(3072 / BN, 8192 / BM), 256, GEMM_SMEM>>>(
        xh, xl, wqh, wql, nullptr, nullptr, qh, ql, 8192, 3072, 1024);

    // MQ=128: 4 query tiles x 256 (bt,h) pairs
    attn_flash_kernel<<<dim3(L_SEQ / 128, 16 * N_HEADS), 256, ATTN_SMEM>>>(rel_emb);

    gemm_bf16x2_kernel<<<dim3(1024 / BN, 8192 / BM), 256, GEMM_SMEM>>>(
        ah, al, woh, wol, b_out, out, nullptr, nullptr, 8192, 1024, 1024);
}

// round 11
// speedup vs baseline: 1.4393x; 1.0078x over previous
#include <cuda_runtime.h>
#include <cuda_bf16.h>
#include <cstdint>

#define L_SEQ 512
#define D_MODEL 1024
#define N_HEADS 16

// ---------------- scratch (__device__ globals) ----------------
__device__ __nv_bfloat16 g_x_hi[(size_t)8192 * 1024];
__device__ __nv_bfloat16 g_x_lo[(size_t)8192 * 1024];
__device__ __nv_bfloat16 g_wqkvT_hi[(size_t)3072 * 1024];
__device__ __nv_bfloat16 g_wqkvT_lo[(size_t)3072 * 1024];
__device__ __nv_bfloat16 g_woutT_hi[(size_t)1024 * 1024];
__device__ __nv_bfloat16 g_woutT_lo[(size_t)1024 * 1024];
__device__ __nv_bfloat16 g_qkv_hi[(size_t)8192 * 3072];
__device__ __nv_bfloat16 g_qkv_lo[(size_t)8192 * 3072];
__device__ __nv_bfloat16 g_attn_hi[(size_t)8192 * 1024];
__device__ __nv_bfloat16 g_attn_lo[(size_t)8192 * 1024];

// ---------------- PTX helpers ----------------
__device__ __forceinline__ uint32_t smem_u32(const void* p) {
    uint32_t a;
    asm("{ .reg .u64 t; cvta.to.shared.u64 t, %1; cvt.u32.u64 %0, t; }" : "=r"(a) : "l"(p));
    return a;
}

#define CP_ASYNC16(dst, src) \
    asm volatile("cp.async.cg.shared.global [%0], [%1], 16;" :: "r"(dst), "l"(src))
#define CP_COMMIT() asm volatile("cp.async.commit_group;" ::: "memory")
#define CP_WAIT1()  asm volatile("cp.async.wait_group 1;" ::: "memory")
#define CP_WAIT0()  asm volatile("cp.async.wait_group 0;" ::: "memory")

#define LDMATRIX_X4(r, addr) \
    asm volatile("ldmatrix.sync.aligned.m8n8.x4.shared.b16 {%0,%1,%2,%3}, [%4];" \
                 : "=r"((r)[0]), "=r"((r)[1]), "=r"((r)[2]), "=r"((r)[3]) : "r"(addr))
#define LDMATRIX_X4_TRANS(r, addr) \
    asm volatile("ldmatrix.sync.aligned.m8n8.x4.trans.shared.b16 {%0,%1,%2,%3}, [%4];" \
                 : "=r"((r)[0]), "=r"((r)[1]), "=r"((r)[2]), "=r"((r)[3]) : "r"(addr))

#define MMA16816(c, a, b) \
    asm volatile("mma.sync.aligned.m16n8k16.row.col.f32.bf16.bf16.f32 " \
                 "{%0,%1,%2,%3},{%4,%5,%6,%7},{%8,%9},{%0,%1,%2,%3};" \
                 : "+f"((c)[0]), "+f"((c)[1]), "+f"((c)[2]), "+f"((c)[3]) \
                 : "r"((a)[0]), "r"((a)[1]), "r"((a)[2]), "r"((a)[3]), \
                   "r"((b)[0]), "r"((b)[1]))

__device__ __forceinline__ uint32_t pack_bf16x2(float a, float b) {
    __nv_bfloat162 t = __floats2bfloat162_rn(a, b);
    return *reinterpret_cast<uint32_t*>(&t);
}

// ---------------- fused prepass: one kernel, 3 phases by blockIdx ----------------
// blocks [0, 32768): x split; [32768, 35840): tsplit w_qkv; [35840, 36864): tsplit w_out
__global__ __launch_bounds__(256) void prepass_kernel(
    const float* __restrict__ x,  __nv_bfloat16* __restrict__ xh,  __nv_bfloat16* __restrict__ xl,
    const float* __restrict__ wq, __nv_bfloat16* __restrict__ wqh, __nv_bfloat16* __restrict__ wql,
    const float* __restrict__ wo, __nv_bfloat16* __restrict__ woh, __nv_bfloat16* __restrict__ wol)
{
    __shared__ float t[32][33];
    const int b = blockIdx.x, tid = threadIdx.x;
    if (b < 32768) {
        int i = b * 256 + tid;   // 32768*256 = 8388608 = 8192*1024 exactly
        float v = x[i];
        __nv_bfloat16 h = __float2bfloat16(v);
        xh[i] = h;
        xl[i] = __float2bfloat16(v - __bfloat162float(h));
    } else {
        const float* in; __nv_bfloat16 *oh, *ol; int R, C, bx, by;
        if (b < 35840) {
            in = wq; oh = wqh; ol = wql; R = 1024; C = 3072;
            int bb = b - 32768; bx = bb % 96; by = bb / 96;
        } else {
            in = wo; oh = woh; ol = wol; R = 1024; C = 1024;
            int bb = b - 35840; bx = bb % 32; by = bb / 32;
        }
        int x0 = tid & 31, y0 = tid >> 5;
        int c0 = bx * 32, r0 = by * 32;
#pragma unroll
        for (int i = 0; i < 32; i += 8)
            t[y0 + i][x0] = in[(size_t)(r0 + y0 + i) * C + c0 + x0];
        __syncthreads();
#pragma unroll
        for (int i = 0; i < 32; i += 8) {
            float v = t[x0][y0 + i];
            __nv_bfloat16 h = __float2bfloat16(v);
            size_t o = (size_t)(c0 + y0 + i) * R + r0 + x0;
            oh[o] = h;
            ol[o] = __float2bfloat16(v - __bfloat162float(h));
        }
    }
}

// ---------------- HMMA bf16x2 GEMM: BK=32, 3-stage, swizzled 64B rows (R7 frozen) ----------------
#define BM 128
#define BN 128
#define BK 32
#define ROW_B 64
#define COMP_BYTES (128 * ROW_B)       // 8192
#define STAGE_BYTES (4 * COMP_BYTES)   // 32768
#define GEMM_SMEM (3 * STAGE_BYTES)    // 98304

__global__ __launch_bounds__(256, 2) void gemm_bf16x2_kernel(
    const __nv_bfloat16* __restrict__ Ahi, const __nv_bfloat16* __restrict__ Alo,
    const __nv_bfloat16* __restrict__ Bhi, const __nv_bfloat16* __restrict__ Blo,
    const float* __restrict__ bias, float* __restrict__ C,
    __nv_bfloat16* __restrict__ Chi, __nv_bfloat16* __restrict__ Clo,
    int M, int N, int K)
{
    extern __shared__ char smem[];
    const uint32_t sbase = smem_u32(smem);
    const int tid = threadIdx.x, wid = tid >> 5, lane = tid & 31;
    const int bm = blockIdx.y * BM, bn = blockIdx.x * BN;
    const int warp_m = (wid >> 2) * 64, warp_n = (wid & 3) * 32;
    const int NT = K / BK;

    float acc[4][4][4];
#pragma unroll
    for (int i = 0; i < 4; i++)
#pragma unroll
        for (int j = 0; j < 4; j++)
#pragma unroll
            for (int r = 0; r < 4; r++) acc[i][j][r] = 0.f;

    const __nv_bfloat16* srcs[4] = {Ahi, Alo, Bhi, Blo};

    auto issue = [&](int s, int kt) {
        const uint32_t dst0 = sbase + s * STAGE_BYTES;
        const int k0 = kt * BK;
#pragma unroll
        for (int comp = 0; comp < 4; comp++) {
            const int rbase = (comp < 2) ? bm : bn;
#pragma unroll
            for (int i = 0; i < 2; i++) {
                int id = i * 256 + tid;
                int row = id >> 2, c = id & 3;
                uint32_t cc = (uint32_t)c ^ ((row >> 1) & 3);
                const __nv_bfloat16* g =
                    srcs[comp] + (size_t)(rbase + row) * K + k0 + c * 8;
                CP_ASYNC16(dst0 + comp * COMP_BYTES + row * ROW_B + cc * 16, g);
            }
        }
    };

    const int lr = lane & 15, lk = lane >> 4;
    const int brow = (lane & 7) + ((lane >> 4) << 3);
    const int bck = (lane >> 3) & 1;

    auto compute = [&](int s) {
        const uint32_t st = sbase + s * STAGE_BYTES;
#pragma unroll
        for (int ks = 0; ks < 2; ks++) {
            uint32_t bh[4][2], bl[4][2];
#pragma unroll
            for (int ntp = 0; ntp < 2; ntp++) {
                int row = warp_n + ntp * 16 + brow;
                uint32_t cidx = (uint32_t)(bck + 2 * ks) ^ ((row >> 1) & 3);
                uint32_t baddr = st + 2 * COMP_BYTES + row * ROW_B + cidx * 16;
                uint32_t r4[4];
                LDMATRIX_X4(r4, baddr);
                bh[2 * ntp][0] = r4[0]; bh[2 * ntp][1] = r4[1];
                bh[2 * ntp + 1][0] = r4[2]; bh[2 * ntp + 1][1] = r4[3];
                LDMATRIX_X4(r4, baddr + COMP_BYTES);
                bl[2 * ntp][0] = r4[0]; bl[2 * ntp][1] = r4[1];
                bl[2 * ntp + 1][0] = r4[2]; bl[2 * ntp + 1][1] = r4[3];
            }
#pragma unroll
            for (int mt = 0; mt < 4; mt++) {
                int row = warp_m + mt * 16 + lr;
                uint32_t cidx = (uint32_t)(lk + 2 * ks) ^ ((row >> 1) & 3);
                uint32_t aaddr = st + row * ROW_B + cidx * 16;
                uint32_t ah[4], al[4];
                LDMATRIX_X4(ah, aaddr);
                LDMATRIX_X4(al, aaddr + COMP_BYTES);
#pragma unroll
                for (int nt = 0; nt < 4; nt++) {
                    MMA16816(acc[mt][nt], ah, bh[nt]);
                    MMA16816(acc[mt][nt], ah, bl[nt]);
                    MMA16816(acc[mt][nt], al, bh[nt]);
                }
            }
        }
    };

    issue(0, 0); CP_COMMIT();
    issue(1, 1); CP_COMMIT();

    int s_kt = 0, s_nx = 2;
    for (int kt = 0; kt < NT; kt++) {
        CP_WAIT1();
        __syncthreads();
        if (kt + 2 < NT) { issue(s_nx, kt + 2); CP_COMMIT(); }
        compute(s_kt);
        s_kt = (s_kt == 2) ? 0 : s_kt + 1;
        s_nx = (s_nx == 2) ? 0 : s_nx + 1;
    }

#pragma unroll
    for (int mt = 0; mt < 4; mt++) {
        int row0 = bm + warp_m + mt * 16 + (lane >> 2);
#pragma unroll
        for (int nt = 0; nt < 4; nt++) {
            int col = bn + warp_n + nt * 8 + 2 * (lane & 3);
            if (Chi) {
#pragma unroll
                for (int half = 0; half < 2; half++) {
                    float v0 = acc[mt][nt][2 * half];
                    float v1 = acc[mt][nt][2 * half + 1];
                    __nv_bfloat16 h0 = __float2bfloat16(v0);
                    __nv_bfloat16 h1 = __float2bfloat16(v1);
                    __nv_bfloat162 hp; hp.x = h0; hp.y = h1;
                    __nv_bfloat162 lp;
                    lp.x = __float2bfloat16(v0 - __bfloat162float(h0));
                    lp.y = __float2bfloat16(v1 - __bfloat162float(h1));
                    size_t o = (size_t)(row0 + half * 8) * N + col;
                    *reinterpret_cast<__nv_bfloat162*>(&Chi[o]) = hp;
                    *reinterpret_cast<__nv_bfloat162*>(&Clo[o]) = lp;
                }
            } else {
                float b0 = 0.f, b1 = 0.f;
                if (bias) { b0 = bias[col]; b1 = bias[col + 1]; }
                float2 v0 = make_float2(acc[mt][nt][0] + b0, acc[mt][nt][1] + b1);
                float2 v1 = make_float2(acc[mt][nt][2] + b0, acc[mt][nt][3] + b1);
                *reinterpret_cast<float2*>(&C[(size_t)row0 * N + col]) = v0;
                *reinterpret_cast<float2*>(&C[(size_t)(row0 + 8) * N + col]) = v1;
            }
        }
    }
}

// ---------------- Fused attention: MQ=128, K double-buffered, PV pipelined by 1 kc ----------------
// smem: KA hi|lo (36864) | V hi|lo (36864) | KB/Q hi|lo (36864) | Rel (1024) = 111616
// Q region becomes KB after fragments move to registers. 2 CTAs/SM.
#define AT_V    36864
#define AT_QB   73728     // Q during prologue; K buffer B afterwards
#define AT_REL  110592
#define ATTN_SMEM 111616

__global__ __launch_bounds__(256, 2) void attn_flash_kernel(const float* __restrict__ rel_emb)
{
    extern __shared__ char smc[];
    const uint32_t sb = smem_u32(smc);
    float* Rel = (float*)(smc + AT_REL);

    const int tid = threadIdx.x, wid = tid >> 5, lane = tid & 31;
    const int pair = blockIdx.y, bt = pair >> 4, h = pair & 15;
    const int q0 = blockIdx.x * 128;
    const int gr = lane >> 2, gc = lane & 3;
    const int lr = lane & 15, lk = lane >> 4;
    const int xrow = (lane & 7) + ((lane >> 4) << 3);        // K ldmatrix X4 row select
    const int xsel = ((lane >> 3) & 1) << 4;                 // K ldmatrix 16B select
    const int vrow = (lane & 7) + (((lane >> 3) & 1) << 3);  // V trans row select
    const int vcol = ((lane >> 4) << 3) * 2;                 // V trans byte select

    const __nv_bfloat16* ghi = g_qkv_hi + (size_t)bt * 512 * 3072 + h * 64;
    const __nv_bfloat16* glo = g_qkv_lo + (size_t)bt * 512 * 3072 + h * 64;

    // K loader into given buffer base (sections: hi | lo, 128x144B each)
    auto issue_k = [&](int t, uint32_t dstbase) {
#pragma unroll
        for (int i = 0; i < 9; i++) {
            int c = i * 256 + tid;
            int sec = c / 1152, rem = c - sec * 1152;
            int row = rem / 9, ch = rem - row * 9;
            const __nv_bfloat16* base = sec ? glo : ghi;
            const __nv_bfloat16* src =
                base + (size_t)(t * 128 + row) * 3072 + 1024 + ch * 8;
            CP_ASYNC16(dstbase + sec * 18432 + row * 144 + ch * 16, src);
        }
    };
    auto issue_v = [&](int t) {
#pragma unroll
        for (int i = 0; i < 9; i++) {
            int c = i * 256 + tid;
            int sec = c / 1152, rem = c - sec * 1152;
            int row = rem / 9, ch = rem - row * 9;
            const __nv_bfloat16* base = sec ? glo : ghi;
            const __nv_bfloat16* src =
                base + (size_t)(t * 128 + row) * 3072 + 2048 + ch * 8;
            CP_ASYNC16(sb + AT_V + sec * 18432 + row * 144 + ch * 16, src);
        }
    };

    issue_k(0, sb); CP_COMMIT();      // K(0) -> buffer A
    issue_v(0); CP_COMMIT();          // V(0)

    // Q tile into region B (scale 0.125 folded — exact), Rel column
    {
        __nv_bfloat16* Qh = (__nv_bfloat16*)(smc + AT_QB);
        __nv_bfloat16* Ql = (__nv_bfloat16*)(smc + AT_QB + 18432);
        for (int idx = tid; idx < 8192; idx += 256) {
            int i = idx >> 6, d = idx & 63;
            size_t g = (size_t)(q0 + i) * 3072 + d;
            Qh[i * 72 + d] = __float2bfloat16(0.125f * __bfloat162float(ghi[g]));
            Ql[i * 72 + d] = __float2bfloat16(0.125f * __bfloat162float(glo[g]));
        }
        if (tid < 255) Rel[tid] = rel_emb[tid * N_HEADS + h];
    }
    CP_WAIT0();          // K(0) + V(0) resident
    __syncthreads();     // + Q/Rel visible

    // Q fragments: persistent (warp's 16 rows)
    uint32_t qh[4][4], ql[4][4];
    {
        uint32_t qa = sb + AT_QB + (wid * 16 + lr) * 144 + lk * 16;
#pragma unroll
        for (int ks = 0; ks < 4; ks++) {
            LDMATRIX_X4(qh[ks], qa + ks * 32);
            LDMATRIX_X4(ql[ks], qa + 18432 + ks * 32);
        }
    }
    __syncthreads();     // all warps got Q frags; region B free for K(1)

    float o[8][4];
#pragma unroll
    for (int n = 0; n < 8; n++)
#pragma unroll
        for (int r = 0; r < 4; r++) o[n][r] = 0.f;
    float sum0 = 0.f, sum1 = 0.f;

    const int gq0 = q0 + wid * 16 + gr;
    const int gq1 = gq0 + 8;

    // PV for one 16-key chunk, given P fragments
    auto pv = [&](int kc, const uint32_t* pfh, const uint32_t* pfl) {
#pragma unroll
        for (int dp = 0; dp < 4; dp++) {
            uint32_t va = sb + AT_V + (kc * 16 + vrow) * 144 + dp * 32 + vcol;
            uint32_t r4[4];
            uint32_t vh0[2], vh1[2], vl0[2], vl1[2];
            LDMATRIX_X4_TRANS(r4, va);
            vh0[0] = r4[0]; vh0[1] = r4[1]; vh1[0] = r4[2]; vh1[1] = r4[3];
            LDMATRIX_X4_TRANS(r4, va + 18432);
            vl0[0] = r4[0]; vl0[1] = r4[1]; vl1[0] = r4[2]; vl1[1] = r4[3];
            MMA16816(o[2 * dp],     pfh, vh0);
            MMA16816(o[2 * dp],     pfh, vl0);
            MMA16816(o[2 * dp],     pfl, vh0);
            MMA16816(o[2 * dp + 1], pfh, vh1);
            MMA16816(o[2 * dp + 1], pfh, vl1);
            MMA16816(o[2 * dp + 1], pfl, vh1);
        }
    };

#pragma unroll 1
    for (int t = 0; t < 4; t++) {
        const uint32_t kb = sb + ((t & 1) ? AT_QB : 0);
        // K(t+1) -> other buffer: hidden behind this entire tile
        if (t < 3) { issue_k(t + 1, sb + ((t & 1) ? 0 : AT_QB)); CP_COMMIT(); }

        uint32_t pfhA[4], pflA[4], pfhB[4], pflB[4];

#pragma unroll
        for (int kc = 0; kc < 8; kc++) {
            // ---- QK(kc) ----
            float acc[2][4];
#pragma unroll
            for (int j = 0; j < 2; j++)
#pragma unroll
                for (int r = 0; r < 4; r++) acc[j][r] = 0.f;

#pragma unroll
            for (int ks = 0; ks < 4; ks++) {
                uint32_t baddr = kb + (kc * 16 + xrow) * 144 + xsel + ks * 32;
                uint32_t r4[4];
                uint32_t bh0[2], bh1[2], bl0[2], bl1[2];
                LDMATRIX_X4(r4, baddr);
                bh0[0] = r4[0]; bh0[1] = r4[1]; bh1[0] = r4[2]; bh1[1] = r4[3];
                LDMATRIX_X4(r4, baddr + 18432);
                bl0[0] = r4[0]; bl0[1] = r4[1]; bl1[0] = r4[2]; bl1[1] = r4[3];
                MMA16816(acc[0], qh[ks], bh0);
                MMA16816(acc[0], qh[ks], bl0);
                MMA16816(acc[0], ql[ks], bh0);
                MMA16816(acc[1], qh[ks], bh1);
                MMA16816(acc[1], qh[ks], bl1);
                MMA16816(acc[1], ql[ks], bh1);
            }

            // ---- bias + exp + running sums -> P frags (ping-pong) ----
            uint32_t* pfh = (kc & 1) ? pfhB : pfhA;
            uint32_t* pfl = (kc & 1) ? pflB : pflA;
#pragma unroll
            for (int j = 0; j < 2; j++) {
                int gs = t * 128 + kc * 16 + j * 8 + 2 * gc;
                float e00 = __expf(acc[j][0] + Rel[min(max(gq0 - gs,     -127), 127) + 127]);
                float e01 = __expf(acc[j][1] + Rel[min(max(gq0 - gs - 1, -127), 127) + 127]);
                float e10 = __expf(acc[j][2] + Rel[min(max(gq1 - gs,     -127), 127) + 127]);
                float e11 = __expf(acc[j][3] + Rel[min(max(gq1 - gs - 1, -127), 127) + 127]);
                sum0 += e00 + e01;
                sum1 += e10 + e11;
                __nv_bfloat162 h0 = __floats2bfloat162_rn(e00, e01);
                __nv_bfloat162 h1 = __floats2bfloat162_rn(e10, e11);
                pfh[2 * j]     = *reinterpret_cast<uint32_t*>(&h0);
                pfh[2 * j + 1] = *reinterpret_cast<uint32_t*>(&h1);
                pfl[2 * j]     = pack_bf16x2(e00 - __bfloat162float(h0.x),
                                             e01 - __bfloat162float(h0.y));
                pfl[2 * j + 1] = pack_bf16x2(e10 - __bfloat162float(h1.x),
                                             e11 - __bfloat162float(h1.y));
            }

            // V(t) readiness gate, placed after QK(0..1) for overlap.
            // t=0: V(0) drained in prologue. t<3: outstanding {V(t),K(t+1)} -> wait1.
            // t=3: outstanding {V(3)} only -> wait0 (R8 lesson).
            if (kc == 1 && t > 0) {
                if (t < 3) { CP_WAIT1(); } else { CP_WAIT0(); }
                __syncthreads();
            }

            // ---- PV(kc-1), one chunk behind ----
            if (kc > 0) {
                if (kc & 1) pv(kc - 1, pfhA, pflA);
                else        pv(kc - 1, pfhB, pflB);
            }
        }
        pv(7, pfhB, pflB);    // kc=7 frags live in B

        // end of tile: all K(t)/V(t) readers done
        __syncthreads();
        if (t < 3) {
            issue_v(t + 1); CP_COMMIT();    // overlaps next tile's QK phase
            CP_WAIT1();                     // outstanding {K(t+1),V(t+1)} -> K(t+1) resident
            __syncthreads();
        }
    }

    // ---- normalize + split-store O ----
    sum0 += __shfl_xor_sync(0xffffffffu, sum0, 1);
    sum0 += __shfl_xor_sync(0xffffffffu, sum0, 2);
    sum1 += __shfl_xor_sync(0xffffffffu, sum1, 1);
    sum1 += __shfl_xor_sync(0xffffffffu, sum1, 2);
    float inv0 = 1.f / sum0, inv1 = 1.f / sum1;

    size_t row0 = (size_t)bt * 512 + gq0;
#pragma unroll
    for (int nt = 0; nt < 8; nt++) {
        int col = h * 64 + nt * 8 + 2 * gc;
        float v0 = o[nt][0] * inv0, v1 = o[nt][1] * inv0;
        float v2 = o[nt][2] * inv1, v3 = o[nt][3] * inv1;
        __nv_bfloat16 a0 = __float2bfloat16(v0), a1 = __float2bfloat16(v1);
        __nv_bfloat16 b0 = __float2bfloat16(v2), b1 = __float2bfloat16(v3);
        __nv_bfloat162 hp0; hp0.x = a0; hp0.y = a1;
        __nv_bfloat162 hp1; hp1.x = b0; hp1.y = b1;
        __nv_bfloat162 lp0;
        lp0.x = __float2bfloat16(v0 - __bfloat162float(a0));
        lp0.y = __float2bfloat16(v1 - __bfloat162float(a1));
        __nv_bfloat162 lp1;
        lp1.x = __float2bfloat16(v2 - __bfloat162float(b0));
        lp1.y = __float2bfloat16(v3 - __bfloat162float(b1));
        *reinterpret_cast<__nv_bfloat162*>(&g_attn_hi[row0 * 1024 + col]) = hp0;
        *reinterpret_cast<__nv_bfloat162*>(&g_attn_lo[row0 * 1024 + col]) = lp0;
        *reinterpret_cast<__nv_bfloat162*>(&g_attn_hi[(row0 + 8) * 1024 + col]) = hp1;
        *reinterpret_cast<__nv_bfloat162*>(&g_attn_lo[(row0 + 8) * 1024 + col]) = lp1;
    }
}

// ---------------- launch ----------------
extern "C" void kernel_launch(void* const* d_in, const int* in_sizes, int n_in,
                              void* d_out, int out_size)
{
    const float* x       = (const float*)d_in[0];
    const float* w_qkv   = (const float*)d_in[1];
    const float* rel_emb = (const float*)d_in[2];
    const float* w_out   = (const float*)d_in[3];
    const float* b_out   = (const float*)d_in[4];
    float* out = (float*)d_out;

    __nv_bfloat16 *xh, *xl, *wqh, *wql, *woh, *wol, *qh, *ql, *ah, *al;
    cudaGetSymbolAddress((void**)&xh, g_x_hi);
    cudaGetSymbolAddress((void**)&xl, g_x_lo);
    cudaGetSymbolAddress((void**)&wqh, g_wqkvT_hi);
    cudaGetSymbolAddress((void**)&wql, g_wqkvT_lo);
    cudaGetSymbolAddress((void**)&woh, g_woutT_hi);
    cudaGetSymbolAddress((void**)&wol, g_woutT_lo);
    cudaGetSymbolAddress((void**)&qh, g_qkv_hi);
    cudaGetSymbolAddress((void**)&ql, g_qkv_lo);
    cudaGetSymbolAddress((void**)&ah, g_attn_hi);
    cudaGetSymbolAddress((void**)&al, g_attn_lo);

    cudaFuncSetAttribute(attn_flash_kernel, cudaFuncAttributeMaxDynamicSharedMemorySize, ATTN_SMEM);
    cudaFuncSetAttribute(gemm_bf16x2_kernel, cudaFuncAttributeMaxDynamicSharedMemorySize, GEMM_SMEM);

    // 0) fused prepass (x split + both weight transposes/splits)
    prepass_kernel<<<36864, 256>>>(x, xh, xl, w_qkv, wqh, wql, w_out, woh, wol);

    // 1) QKV projection -> bf16 hi/lo qkv
    gemm_bf16x2_kernel<<<dim3(3072 / BN, 8192 / BM), 256, GEMM_SMEM>>>(
        xh, xl, wqh, wql, nullptr, nullptr, qh, ql, 8192, 3072, 1024);

    // 2) fused attention (MQ=128, K double-buffered)
    attn_flash_kernel<<<dim3(L_SEQ / 128, 16 * N_HEADS), 256, ATTN_SMEM>>>(rel_emb);

    // 3) output projection (fp32 out + bias)
    gemm_bf16x2_kernel<<<dim3(1024 / BN, 8192 / BM), 256, GEMM_SMEM>>>(
        ah, al, woh, wol, b_out, out, nullptr, nullptr, 8192, 1024, 1024);
}

// round 12
// speedup vs baseline: 1.4794x; 1.0278x over previous
#include <cuda_runtime.h>
#include <cuda_bf16.h>
#include <cstdint>

#define L_SEQ 512
#define D_MODEL 1024
#define N_HEADS 16

// ---------------- scratch (__device__ globals) ----------------
__device__ __nv_bfloat16 g_x_hi[(size_t)8192 * 1024];
__device__ __nv_bfloat16 g_x_lo[(size_t)8192 * 1024];
__device__ __nv_bfloat16 g_wqkvT_hi[(size_t)3072 * 1024];
__device__ __nv_bfloat16 g_wqkvT_lo[(size_t)3072 * 1024];
__device__ __nv_bfloat16 g_woutT_hi[(size_t)1024 * 1024];
__device__ __nv_bfloat16 g_woutT_lo[(size_t)1024 * 1024];
__device__ __nv_bfloat16 g_qkv_hi[(size_t)8192 * 3072];
__device__ __nv_bfloat16 g_qkv_lo[(size_t)8192 * 3072];
__device__ __nv_bfloat16 g_attn_hi[(size_t)8192 * 1024];
__device__ __nv_bfloat16 g_attn_lo[(size_t)8192 * 1024];

// ---------------- PTX helpers ----------------
__device__ __forceinline__ uint32_t smem_u32(const void* p) {
    uint32_t a;
    asm("{ .reg .u64 t; cvta.to.shared.u64 t, %1; cvt.u32.u64 %0, t; }" : "=r"(a) : "l"(p));
    return a;
}

#define CP_ASYNC16(dst, src) \
    asm volatile("cp.async.cg.shared.global [%0], [%1], 16;" :: "r"(dst), "l"(src))
#define CP_COMMIT() asm volatile("cp.async.commit_group;" ::: "memory")
#define CP_WAIT1()  asm volatile("cp.async.wait_group 1;" ::: "memory")
#define CP_WAIT0()  asm volatile("cp.async.wait_group 0;" ::: "memory")

#define LDMATRIX_X4(r, addr) \
    asm volatile("ldmatrix.sync.aligned.m8n8.x4.shared.b16 {%0,%1,%2,%3}, [%4];" \
                 : "=r"((r)[0]), "=r"((r)[1]), "=r"((r)[2]), "=r"((r)[3]) : "r"(addr))
#define LDMATRIX_X4_TRANS(r, addr) \
    asm volatile("ldmatrix.sync.aligned.m8n8.x4.trans.shared.b16 {%0,%1,%2,%3}, [%4];" \
                 : "=r"((r)[0]), "=r"((r)[1]), "=r"((r)[2]), "=r"((r)[3]) : "r"(addr))

#define MMA16816(c, a, b) \
    asm volatile("mma.sync.aligned.m16n8k16.row.col.f32.bf16.bf16.f32 " \
                 "{%0,%1,%2,%3},{%4,%5,%6,%7},{%8,%9},{%0,%1,%2,%3};" \
                 : "+f"((c)[0]), "+f"((c)[1]), "+f"((c)[2]), "+f"((c)[3]) \
                 : "r"((a)[0]), "r"((a)[1]), "r"((a)[2]), "r"((a)[3]), \
                   "r"((b)[0]), "r"((b)[1]))

__device__ __forceinline__ uint32_t pack_bf16x2(float a, float b) {
    __nv_bfloat162 t = __floats2bfloat162_rn(a, b);
    return *reinterpret_cast<uint32_t*>(&t);
}

// ---------------- fused prepass: one kernel, 3 phases by blockIdx ----------------
__global__ __launch_bounds__(256) void prepass_kernel(
    const float* __restrict__ x,  __nv_bfloat16* __restrict__ xh,  __nv_bfloat16* __restrict__ xl,
    const float* __restrict__ wq, __nv_bfloat16* __restrict__ wqh, __nv_bfloat16* __restrict__ wql,
    const float* __restrict__ wo, __nv_bfloat16* __restrict__ woh, __nv_bfloat16* __restrict__ wol)
{
    __shared__ float t[32][33];
    const int b = blockIdx.x, tid = threadIdx.x;
    if (b < 32768) {
        int i = b * 256 + tid;
        float v = x[i];
        __nv_bfloat16 h = __float2bfloat16(v);
        xh[i] = h;
        xl[i] = __float2bfloat16(v - __bfloat162float(h));
    } else {
        const float* in; __nv_bfloat16 *oh, *ol; int R, C, bx, by;
        if (b < 35840) {
            in = wq; oh = wqh; ol = wql; R = 1024; C = 3072;
            int bb = b - 32768; bx = bb % 96; by = bb / 96;
        } else {
            in = wo; oh = woh; ol = wol; R = 1024; C = 1024;
            int bb = b - 35840; bx = bb % 32; by = bb / 32;
        }
        int x0 = tid & 31, y0 = tid >> 5;
        int c0 = bx * 32, r0 = by * 32;
#pragma unroll
        for (int i = 0; i < 32; i += 8)
            t[y0 + i][x0] = in[(size_t)(r0 + y0 + i) * C + c0 + x0];
        __syncthreads();
#pragma unroll
        for (int i = 0; i < 32; i += 8) {
            float v = t[x0][y0 + i];
            __nv_bfloat16 h = __float2bfloat16(v);
            size_t o = (size_t)(c0 + y0 + i) * R + r0 + x0;
            oh[o] = h;
            ol[o] = __float2bfloat16(v - __bfloat162float(h));
        }
    }
}

// ---------------- HMMA bf16x2 GEMM: BK=32, 3-stage, swizzled 64B rows ----------------
// R12: cp.async issue interleaved into compute; final-iteration wait0 (race fix).
#define BM 128
#define BN 128
#define BK 32
#define ROW_B 64
#define COMP_BYTES (128 * ROW_B)       // 8192
#define STAGE_BYTES (4 * COMP_BYTES)   // 32768
#define GEMM_SMEM (3 * STAGE_BYTES)    // 98304

__global__ __launch_bounds__(256, 2) void gemm_bf16x2_kernel(
    const __nv_bfloat16* __restrict__ Ahi, const __nv_bfloat16* __restrict__ Alo,
    const __nv_bfloat16* __restrict__ Bhi, const __nv_bfloat16* __restrict__ Blo,
    const float* __restrict__ bias, float* __restrict__ C,
    __nv_bfloat16* __restrict__ Chi, __nv_bfloat16* __restrict__ Clo,
    int M, int N, int K)
{
    extern __shared__ char smem[];
    const uint32_t sbase = smem_u32(smem);
    const int tid = threadIdx.x, wid = tid >> 5, lane = tid & 31;
    const int bm = blockIdx.y * BM, bn = blockIdx.x * BN;
    const int warp_m = (wid >> 2) * 64, warp_n = (wid & 3) * 32;
    const int NT = K / BK;

    float acc[4][4][4];
#pragma unroll
    for (int i = 0; i < 4; i++)
#pragma unroll
        for (int j = 0; j < 4; j++)
#pragma unroll
            for (int r = 0; r < 4; r++) acc[i][j][r] = 0.f;

    const __nv_bfloat16* srcs[4] = {Ahi, Alo, Bhi, Blo};

    auto issue = [&](int s, int kt) {
        const uint32_t dst0 = sbase + s * STAGE_BYTES;
        const int k0 = kt * BK;
#pragma unroll
        for (int comp = 0; comp < 4; comp++) {
            const int rbase = (comp < 2) ? bm : bn;
#pragma unroll
            for (int i = 0; i < 2; i++) {
                int id = i * 256 + tid;
                int row = id >> 2, c = id & 3;
                uint32_t cc = (uint32_t)c ^ ((row >> 1) & 3);
                const __nv_bfloat16* g =
                    srcs[comp] + (size_t)(rbase + row) * K + k0 + c * 8;
                CP_ASYNC16(dst0 + comp * COMP_BYTES + row * ROW_B + cc * 16, g);
            }
        }
    };

    const int lr = lane & 15, lk = lane >> 4;
    const int brow = (lane & 7) + ((lane >> 4) << 3);
    const int bck = (lane >> 3) & 1;

    // compute one stage; cp.async issue for tile kt2 interleaved after mt==0 of ks==0
    auto compute = [&](int s, int snx, int kt2, bool do_issue) {
        const uint32_t st = sbase + s * STAGE_BYTES;
#pragma unroll
        for (int ks = 0; ks < 2; ks++) {
            uint32_t bh[4][2], bl[4][2];
#pragma unroll
            for (int ntp = 0; ntp < 2; ntp++) {
                int row = warp_n + ntp * 16 + brow;
                uint32_t cidx = (uint32_t)(bck + 2 * ks) ^ ((row >> 1) & 3);
                uint32_t baddr = st + 2 * COMP_BYTES + row * ROW_B + cidx * 16;
                uint32_t r4[4];
                LDMATRIX_X4(r4, baddr);
                bh[2 * ntp][0] = r4[0]; bh[2 * ntp][1] = r4[1];
                bh[2 * ntp + 1][0] = r4[2]; bh[2 * ntp + 1][1] = r4[3];
                LDMATRIX_X4(r4, baddr + COMP_BYTES);
                bl[2 * ntp][0] = r4[0]; bl[2 * ntp][1] = r4[1];
                bl[2 * ntp + 1][0] = r4[2]; bl[2 * ntp + 1][1] = r4[3];
            }
#pragma unroll
            for (int mt = 0; mt < 4; mt++) {
                int row = warp_m + mt * 16 + lr;
                uint32_t cidx = (uint32_t)(lk + 2 * ks) ^ ((row >> 1) & 3);
                uint32_t aaddr = st + row * ROW_B + cidx * 16;
                uint32_t ah[4], al[4];
                LDMATRIX_X4(ah, aaddr);
                LDMATRIX_X4(al, aaddr + COMP_BYTES);
#pragma unroll
                for (int nt = 0; nt < 4; nt++) {
                    MMA16816(acc[mt][nt], ah, bh[nt]);
                    MMA16816(acc[mt][nt], ah, bl[nt]);
                    MMA16816(acc[mt][nt], al, bh[nt]);
                }
                if (ks == 0 && mt == 0 && do_issue) {
                    issue(snx, kt2);
                    CP_COMMIT();
                }
            }
        }
    };

    issue(0, 0); CP_COMMIT();
    issue(1, 1); CP_COMMIT();

    int s_kt = 0, s_nx = 2;
    for (int kt = 0; kt < NT; kt++) {
        if (kt == NT - 1) { CP_WAIT0(); }   // final tile: newest group IS this tile (race fix)
        else              { CP_WAIT1(); }
        __syncthreads();
        compute(s_kt, s_nx, kt + 2, kt + 2 < NT);
        s_kt = (s_kt == 2) ? 0 : s_kt + 1;
        s_nx = (s_nx == 2) ? 0 : s_nx + 1;
    }

#pragma unroll
    for (int mt = 0; mt < 4; mt++) {
        int row0 = bm + warp_m + mt * 16 + (lane >> 2);
#pragma unroll
        for (int nt = 0; nt < 4; nt++) {
            int col = bn + warp_n + nt * 8 + 2 * (lane & 3);
            if (Chi) {
#pragma unroll
                for (int half = 0; half < 2; half++) {
                    float v0 = acc[mt][nt][2 * half];
                    float v1 = acc[mt][nt][2 * half + 1];
                    __nv_bfloat16 h0 = __float2bfloat16(v0);
                    __nv_bfloat16 h1 = __float2bfloat16(v1);
                    __nv_bfloat162 hp; hp.x = h0; hp.y = h1;
                    __nv_bfloat162 lp;
                    lp.x = __float2bfloat16(v0 - __bfloat162float(h0));
                    lp.y = __float2bfloat16(v1 - __bfloat162float(h1));
                    size_t o = (size_t)(row0 + half * 8) * N + col;
                    *reinterpret_cast<__nv_bfloat162*>(&Chi[o]) = hp;
                    *reinterpret_cast<__nv_bfloat162*>(&Clo[o]) = lp;
                }
            } else {
                float b0 = 0.f, b1 = 0.f;
                if (bias) { b0 = bias[col]; b1 = bias[col + 1]; }
                float2 v0 = make_float2(acc[mt][nt][0] + b0, acc[mt][nt][1] + b1);
                float2 v1 = make_float2(acc[mt][nt][2] + b0, acc[mt][nt][3] + b1);
                *reinterpret_cast<float2*>(&C[(size_t)row0 * N + col]) = v0;
                *reinterpret_cast<float2*>(&C[(size_t)(row0 + 8) * N + col]) = v1;
            }
        }
    }
}

// ---------------- Fused attention: MQ=128, K double-buffered, pre-clamped Rel table ----------------
// smem: KA hi|lo (36864) | V hi|lo (36864) | KB/Q hi|lo (36864) | Rel2[640] (2560) = 113152
#define AT_V    36864
#define AT_QB   73728
#define AT_REL  110592
#define ATTN_SMEM 113152

__global__ __launch_bounds__(256, 2) void attn_flash_kernel(const float* __restrict__ rel_emb)
{
    extern __shared__ char smc[];
    const uint32_t sb = smem_u32(smc);
    float* Rel2 = (float*)(smc + AT_REL);   // Rel2[idx] = rel_emb[clamp(idx + q0 - 511)]

    const int tid = threadIdx.x, wid = tid >> 5, lane = tid & 31;
    const int pair = blockIdx.y, bt = pair >> 4, h = pair & 15;
    const int q0 = blockIdx.x * 128;
    const int gr = lane >> 2, gc = lane & 3;
    const int lr = lane & 15, lk = lane >> 4;
    const int xrow = (lane & 7) + ((lane >> 4) << 3);
    const int xsel = ((lane >> 3) & 1) << 4;
    const int vrow = (lane & 7) + (((lane >> 3) & 1) << 3);
    const int vcol = ((lane >> 4) << 3) * 2;

    const __nv_bfloat16* ghi = g_qkv_hi + (size_t)bt * 512 * 3072 + h * 64;
    const __nv_bfloat16* glo = g_qkv_lo + (size_t)bt * 512 * 3072 + h * 64;

    auto issue_k = [&](int t, uint32_t dstbase) {
#pragma unroll
        for (int i = 0; i < 9; i++) {
            int c = i * 256 + tid;
            int sec = c / 1152, rem = c - sec * 1152;
            int row = rem / 9, ch = rem - row * 9;
            const __nv_bfloat16* base = sec ? glo : ghi;
            const __nv_bfloat16* src =
                base + (size_t)(t * 128 + row) * 3072 + 1024 + ch * 8;
            CP_ASYNC16(dstbase + sec * 18432 + row * 144 + ch * 16, src);
        }
    };
    auto issue_v = [&](int t) {
#pragma unroll
        for (int i = 0; i < 9; i++) {
            int c = i * 256 + tid;
            int sec = c / 1152, rem = c - sec * 1152;
            int row = rem / 9, ch = rem - row * 9;
            const __nv_bfloat16* base = sec ? glo : ghi;
            const __nv_bfloat16* src =
                base + (size_t)(t * 128 + row) * 3072 + 2048 + ch * 8;
            CP_ASYNC16(sb + AT_V + sec * 18432 + row * 144 + ch * 16, src);
        }
    };

    issue_k(0, sb); CP_COMMIT();
    issue_v(0); CP_COMMIT();

    // Q tile into region B (scale 0.125 folded — exact); pre-clamped Rel2 table
    {
        __nv_bfloat16* Qh = (__nv_bfloat16*)(smc + AT_QB);
        __nv_bfloat16* Ql = (__nv_bfloat16*)(smc + AT_QB + 18432);
        for (int idx = tid; idx < 8192; idx += 256) {
            int i = idx >> 6, d = idx & 63;
            size_t g = (size_t)(q0 + i) * 3072 + d;
            Qh[i * 72 + d] = __float2bfloat16(0.125f * __bfloat162float(ghi[g]));
            Ql[i * 72 + d] = __float2bfloat16(0.125f * __bfloat162float(glo[g]));
        }
        // Rel2[idx] covers d = gq-gs in [q0-511, q0+127]; idx = d - q0 + 511 in [0,638]
        for (int idx = tid; idx < 639; idx += 256) {
            int d = idx + q0 - 511;
            int cl = min(max(d, -127), 127) + 127;
            Rel2[idx] = rel_emb[cl * N_HEADS + h];
        }
    }
    CP_WAIT0();
    __syncthreads();

    uint32_t qh[4][4], ql[4][4];
    {
        uint32_t qa = sb + AT_QB + (wid * 16 + lr) * 144 + lk * 16;
#pragma unroll
        for (int ks = 0; ks < 4; ks++) {
            LDMATRIX_X4(qh[ks], qa + ks * 32);
            LDMATRIX_X4(ql[ks], qa + 18432 + ks * 32);
        }
    }
    __syncthreads();     // region B free for K(1)

    float o[8][4];
#pragma unroll
    for (int n = 0; n < 8; n++)
#pragma unroll
        for (int r = 0; r < 4; r++) o[n][r] = 0.f;
    float sum0 = 0.f, sum1 = 0.f;

    const int gq0 = q0 + wid * 16 + gr;
    // Rel2 base index for (gq0, gs=0): C0 = gq0 - q0 + 511; lookup idx = C0 - gs
    const int C0 = wid * 16 + gr + 511;

    auto pv = [&](int kc, const uint32_t* pfh, const uint32_t* pfl) {
#pragma unroll
        for (int dp = 0; dp < 4; dp++) {
            uint32_t va = sb + AT_V + (kc * 16 + vrow) * 144 + dp * 32 + vcol;
            uint32_t r4[4];
            uint32_t vh0[2], vh1[2], vl0[2], vl1[2];
            LDMATRIX_X4_TRANS(r4, va);
            vh0[0] = r4[0]; vh0[1] = r4[1]; vh1[0] = r4[2]; vh1[1] = r4[3];
            LDMATRIX_X4_TRANS(r4, va + 18432);
            vl0[0] = r4[0]; vl0[1] = r4[1]; vl1[0] = r4[2]; vl1[1] = r4[3];
            MMA16816(o[2 * dp],     pfh, vh0);
            MMA16816(o[2 * dp],     pfh, vl0);
            MMA16816(o[2 * dp],     pfl, vh0);
            MMA16816(o[2 * dp + 1], pfh, vh1);
            MMA16816(o[2 * dp + 1], pfh, vl1);
            MMA16816(o[2 * dp + 1], pfl, vh1);
        }
    };

#pragma unroll 1
    for (int t = 0; t < 4; t++) {
        const uint32_t kb = sb + ((t & 1) ? AT_QB : 0);
        if (t < 3) { issue_k(t + 1, sb + ((t & 1) ? 0 : AT_QB)); CP_COMMIT(); }

        uint32_t pfhA[4], pflA[4], pfhB[4], pflB[4];

#pragma unroll
        for (int kc = 0; kc < 8; kc++) {
            float acc[2][4];
#pragma unroll
            for (int j = 0; j < 2; j++)
#pragma unroll
                for (int r = 0; r < 4; r++) acc[j][r] = 0.f;

#pragma unroll
            for (int ks = 0; ks < 4; ks++) {
                uint32_t baddr = kb + (kc * 16 + xrow) * 144 + xsel + ks * 32;
                uint32_t r4[4];
                uint32_t bh0[2], bh1[2], bl0[2], bl1[2];
                LDMATRIX_X4(r4, baddr);
                bh0[0] = r4[0]; bh0[1] = r4[1]; bh1[0] = r4[2]; bh1[1] = r4[3];
                LDMATRIX_X4(r4, baddr + 18432);
                bl0[0] = r4[0]; bl0[1] = r4[1]; bl1[0] = r4[2]; bl1[1] = r4[3];
                MMA16816(acc[0], qh[ks], bh0);
                MMA16816(acc[0], qh[ks], bl0);
                MMA16816(acc[0], ql[ks], bh0);
                MMA16816(acc[1], qh[ks], bh1);
                MMA16816(acc[1], qh[ks], bl1);
                MMA16816(acc[1], ql[ks], bh1);
            }

            uint32_t* pfh = (kc & 1) ? pfhB : pfhA;
            uint32_t* pfl = (kc & 1) ? pflB : pflA;
#pragma unroll
            for (int j = 0; j < 2; j++) {
                int gs = t * 128 + kc * 16 + j * 8 + 2 * gc;
                int i00 = C0 - gs;                     // pre-clamped table
                float e00 = __expf(acc[j][0] + Rel2[i00]);
                float e01 = __expf(acc[j][1] + Rel2[i00 - 1]);
                float e10 = __expf(acc[j][2] + Rel2[i00 + 8]);
                float e11 = __expf(acc[j][3] + Rel2[i00 + 7]);
                sum0 += e00 + e01;
                sum1 += e10 + e11;
                __nv_bfloat162 h0 = __floats2bfloat162_rn(e00, e01);
                __nv_bfloat162 h1 = __floats2bfloat162_rn(e10, e11);
                pfh[2 * j]     = *reinterpret_cast<uint32_t*>(&h0);
                pfh[2 * j + 1] = *reinterpret_cast<uint32_t*>(&h1);
                pfl[2 * j]     = pack_bf16x2(e00 - __bfloat162float(h0.x),
                                             e01 - __bfloat162float(h0.y));
                pfl[2 * j + 1] = pack_bf16x2(e10 - __bfloat162float(h1.x),
                                             e11 - __bfloat162float(h1.y));
            }

            if (kc == 1 && t > 0) {
                if (t < 3) { CP_WAIT1(); } else { CP_WAIT0(); }
                __syncthreads();
            }

            if (kc > 0) {
                if (kc & 1) pv(kc - 1, pfhA, pflA);
                else        pv(kc - 1, pfhB, pflB);
            }
        }
        pv(7, pfhB, pflB);

        __syncthreads();
        if (t < 3) {
            issue_v(t + 1); CP_COMMIT();
            CP_WAIT1();
            __syncthreads();
        }
    }

    sum0 += __shfl_xor_sync(0xffffffffu, sum0, 1);
    sum0 += __shfl_xor_sync(0xffffffffu, sum0, 2);
    sum1 += __shfl_xor_sync(0xffffffffu, sum1, 1);
    sum1 += __shfl_xor_sync(0xffffffffu, sum1, 2);
    float inv0 = 1.f / sum0, inv1 = 1.f / sum1;

    size_t row0 = (size_t)bt * 512 + gq0;
#pragma unroll
    for (int nt = 0; nt < 8; nt++) {
        int col = h * 64 + nt * 8 + 2 * gc;
        float v0 = o[nt][0] * inv0, v1 = o[nt][1] * inv0;
        float v2 = o[nt][2] * inv1, v3 = o[nt][3] * inv1;
        __nv_bfloat16 a0 = __float2bfloat16(v0), a1 = __float2bfloat16(v1);
        __nv_bfloat16 b0 = __float2bfloat16(v2), b1 = __float2bfloat16(v3);
        __nv_bfloat162 hp0; hp0.x = a0; hp0.y = a1;
        __nv_bfloat162 hp1; hp1.x = b0; hp1.y = b1;
        __nv_bfloat162 lp0;
        lp0.x = __float2bfloat16(v0 - __bfloat162float(a0));
        lp0.y = __float2bfloat16(v1 - __bfloat162float(a1));
        __nv_bfloat162 lp1;
        lp1.x = __float2bfloat16(v2 - __bfloat162float(b0));
        lp1.y = __float2bfloat16(v3 - __bfloat162float(b1));
        *reinterpret_cast<__nv_bfloat162*>(&g_attn_hi[row0 * 1024 + col]) = hp0;
        *reinterpret_cast<__nv_bfloat162*>(&g_attn_lo[row0 * 1024 + col]) = lp0;
        *reinterpret_cast<__nv_bfloat162*>(&g_attn_hi[(row0 + 8) * 1024 + col]) = hp1;
        *reinterpret_cast<__nv_bfloat162*>(&g_attn_lo[(row0 + 8) * 1024 + col]) = lp1;
    }
}

// ---------------- launch ----------------
extern "C" void kernel_launch(void* const* d_in, const int* in_sizes, int n_in,
                              void* d_out, int out_size)
{
    const float* x       = (const float*)d_in[0];
    const float* w_qkv   = (const float*)d_in[1];
    const float* rel_emb = (const float*)d_in[2];
    const float* w_out   = (const float*)d_in[3];
    const float* b_out   = (const float*)d_in[4];
    float* out = (float*)d_out;

    __nv_bfloat16 *xh, *xl, *wqh, *wql, *woh, *wol, *qh, *ql, *ah, *al;
    cudaGetSymbolAddress((void**)&xh, g_x_hi);
    cudaGetSymbolAddress((void**)&xl, g_x_lo);
    cudaGetSymbolAddress((void**)&wqh, g_wqkvT_hi);
    cudaGetSymbolAddress((void**)&wql, g_wqkvT_lo);
    cudaGetSymbolAddress((void**)&woh, g_woutT_hi);
    cudaGetSymbolAddress((void**)&wol, g_woutT_lo);
    cudaGetSymbolAddress((void**)&qh, g_qkv_hi);
    cudaGetSymbolAddress((void**)&ql, g_qkv_lo);
    cudaGetSymbolAddress((void**)&ah, g_attn_hi);
    cudaGetSymbolAddress((void**)&al, g_attn_lo);

    cudaFuncSetAttribute(attn_flash_kernel, cudaFuncAttributeMaxDynamicSharedMemorySize, ATTN_SMEM);
    cudaFuncSetAttribute(gemm_bf16x2_kernel, cudaFuncAttributeMaxDynamicSharedMemorySize, GEMM_SMEM);

    prepass_kernel<<<36864, 256>>>(x, xh, xl, w_qkv, wqh, wql, w_out, woh, wol);

    gemm_bf16x2_kernel<<<dim3(3072 / BN, 8192 / BM), 256, GEMM_SMEM>>>(
        xh, xl, wqh, wql, nullptr, nullptr, qh, ql, 8192, 3072, 1024);

    attn_flash_kernel<<<dim3(L_SEQ / 128, 16 * N_HEADS), 256, ATTN_SMEM>>>(rel_emb);

    gemm_bf16x2_kernel<<<dim3(1024 / BN, 8192 / BM), 256, GEMM_SMEM>>>(
        ah, al, woh, wol, b_out, out, nullptr, nullptr, 8192, 1024, 1024);
}